// round 7
// baseline (speedup 1.0000x reference)
#include <cuda_runtime.h>
#include <math.h>

#define VOCAB 32000
#define D_IN  512
#define D_H   1024
#define D3H   3072
#define D_OUT 64
#define BB    64
#define SS    256
#define NCTA  128

typedef unsigned long long u64t;

// ---------------- scratch (static device globals; zero-init at load) ----------
// gi transposed: [3H rows][S*B cols]  (row = gate*1024+j, col = s*64+b)
__device__ float g_gi[(size_t)D3H * SS * BB];
// h transposed: [s][j][b]
__device__ float g_hs[(size_t)SS * D_H * BB];
__device__ float g_h0[D_H * BB];                // all-zero h(-1), never written

// ---------------- distributed progress flags (monotonic across replays) -------
__device__ unsigned g_prog[NCTA];               // g_prog[c] only written by CTA c

// ---------------- f32x2 helpers ------------------------------------------------
__device__ __forceinline__ void fma2(u64t& c, u64t a, u64t b) {
    asm("fma.rn.f32x2 %0, %1, %2, %0;" : "+l"(c) : "l"(a), "l"(b));
}
__device__ __forceinline__ float2 up2(u64t v) {
    float2 r;
    asm("mov.b64 {%0, %1}, %2;" : "=f"(r.x), "=f"(r.y) : "l"(v));
    return r;
}
__device__ __forceinline__ u64t dup64(float w) {
    u64t r;
    asm("mov.b64 %0, {%1, %1};" : "=l"(r) : "f"(w));
    return r;
}

// ==============================================================================
// Kernel 1: g_gi[n][m] = sum_d w_ih[n][d] * emb[x(m)][d] + b_ih[n]   (unchanged)
// ==============================================================================
__global__ __launch_bounds__(256) void gi_gemm(
    const int* __restrict__ x, const float* __restrict__ emb,
    const float* __restrict__ w_ih, const float* __restrict__ b_ih)
{
    __shared__ float2 As2[16][128];   // 16 KB (w_ih side, duplicated)
    __shared__ float  Bs [16][128];   //  8 KB (gathered emb side)

    const int tid   = threadIdx.x;
    const int m_blk = blockIdx.y * 128;    // w_ih rows
    const int n_blk = blockIdx.x * 128;    // token cols

    const float* aptr[2]; int arow[2], akq[2];
    const float* bptr[2];
#pragma unroll
    for (int t = 0; t < 2; t++) {
        int i   = tid + t * 256;            // 0..511
        arow[t] = i >> 2;                   // 0..127
        akq[t]  = (i & 3) * 4;
        aptr[t] = w_ih + (size_t)(m_blk + arow[t]) * D_IN;
        int n = n_blk + arow[t];
        int s = n >> 6, b = n & 63;         // n = s*B + b
        int tok = x[b * SS + s];
        bptr[t] = emb + (size_t)tok * D_IN;
    }

    u64t c2[8][4];
#pragma unroll
    for (int i = 0; i < 8; i++)
#pragma unroll
        for (int j = 0; j < 4; j++) c2[i][j] = 0ull;

    const int ty = tid >> 4, tx = tid & 15;

    for (int kt = 0; kt < D_IN; kt += 16) {
#pragma unroll
        for (int t = 0; t < 2; t++) {
            float4 v = *(const float4*)(aptr[t] + kt + akq[t]);
            As2[akq[t]+0][arow[t]] = make_float2(v.x, v.x);
            As2[akq[t]+1][arow[t]] = make_float2(v.y, v.y);
            As2[akq[t]+2][arow[t]] = make_float2(v.z, v.z);
            As2[akq[t]+3][arow[t]] = make_float2(v.w, v.w);
            float4 w = *(const float4*)(bptr[t] + kt + akq[t]);
            Bs[akq[t]+0][arow[t]] = w.x;
            Bs[akq[t]+1][arow[t]] = w.y;
            Bs[akq[t]+2][arow[t]] = w.z;
            Bs[akq[t]+3][arow[t]] = w.w;
        }
        __syncthreads();
#pragma unroll
        for (int k = 0; k < 16; k++) {
            u64t ad[8], bb[4];
#pragma unroll
            for (int i = 0; i < 4; i++) {
                ad[i]     = *(const u64t*)&As2[k][ty*4 + i];
                ad[i + 4] = *(const u64t*)&As2[k][64 + ty*4 + i];
            }
            bb[0] = *(const u64t*)&Bs[k][tx*4];
            bb[1] = *(const u64t*)&Bs[k][tx*4 + 2];
            bb[2] = *(const u64t*)&Bs[k][64 + tx*4];
            bb[3] = *(const u64t*)&Bs[k][64 + tx*4 + 2];
#pragma unroll
            for (int i = 0; i < 8; i++)
#pragma unroll
                for (int j = 0; j < 4; j++)
                    fma2(c2[i][j], ad[i], bb[j]);
        }
        __syncthreads();
    }

#pragma unroll
    for (int i = 0; i < 8; i++) {
        int mi = (i < 4) ? (ty*4 + i) : (64 + ty*4 + (i - 4));
        size_t m = (size_t)(m_blk + mi);
        float bih = b_ih[m];
#pragma unroll
        for (int j = 0; j < 4; j++) {
            int nj = (j < 2) ? (tx*4 + j*2) : (64 + tx*4 + (j - 2)*2);
            int n  = n_blk + nj;
            float2 v = up2(c2[i][j]);
            v.x += bih;
            v.y += bih;
            *(float2*)(g_gi + m * (SS * BB) + n) = v;
        }
    }
}

// ==============================================================================
// Kernel 2: PERSISTENT GRU. 128 CTAs x 256 threads, 1 CTA/SM.
// Conflict-free SMEM mainloop; STS overlapped mid-tile; distributed-flag
// step synchronization (no contended atomic, no central release).
// ==============================================================================
#define REDSTRIDE 68

__global__ void __launch_bounds__(256, 1) gru_persistent(
    const float* __restrict__ w_hh, const float* __restrict__ b_hh)
{
    extern __shared__ float smem[];
    float* ws01f = smem;                      // [1024][16]  (g0,g1 pairs) 64 KB
    float* ws2f  = smem + 16384;              // [1024][8]   (g2 pairs)    32 KB
    float* buf0  = smem + 24576;              // [128][128] dup            64 KB
    float* buf1  = smem + 24576 + 16384;      // [128][128] dup            64 KB
    float* red   = buf0;                      // [96][68]                  26 KB (aliases buf0)
    u64t* ws01 = (u64t*)ws01f;
    u64t* ws2  = (u64t*)ws2f;
    __shared__ unsigned s_base;

    const int tid  = threadIdx.x;
    const int j0   = blockIdx.x * 8;
    const int wid  = tid >> 5;
    const int lane = tid & 31;
    // dup-store float offset within a 128-float dup row:
    // even lane 2d  -> b-pair (4d,4d+1)   at float 4d            (region 1)
    // odd  lane 2d+1-> b-pair (4d+2,4d+3) at float 64 + 4*sigma(d), sigma(d)=((d+4)&7)|(d&8)
    const int dhalf  = lane >> 1;
    const int sig_l  = ((dhalf + 4) & 7) | (dhalf & 8);
    const int dupoff = (lane & 1) ? (64 + 4 * sig_l) : (4 * dhalf);

    // ---- preload weight slice into split layout:
    //   ws01 u64[k*8 + jp*2 + g] = (w[g][j0+2jp], w[g][j0+2jp+1]) for g in {0,1}
    //   ws2  u64[k*4 + jp]       = (w[2][j0+2jp], w[2][j0+2jp+1])
    for (int idx = tid; idx < 24 * 256; idx += 256) {
        int r = idx >> 8;            // 0..23
        int q = idx & 255;           // k quad
        int g = r >> 3, jj = r & 7;
        int jp = jj >> 1, e = jj & 1;
        float4 v = *(const float4*)(w_hh + (size_t)(g * D_H + j0 + jj) * D_H + q * 4);
        if (g < 2) {
            int o = 4 * jp + 2 * g + e;
            ws01f[(q*4+0)*16 + o] = v.x;
            ws01f[(q*4+1)*16 + o] = v.y;
            ws01f[(q*4+2)*16 + o] = v.z;
            ws01f[(q*4+3)*16 + o] = v.w;
        } else {
            int o = 2 * jp + e;
            ws2f[(q*4+0)*8 + o] = v.x;
            ws2f[(q*4+1)*8 + o] = v.y;
            ws2f[(q*4+2)*8 + o] = v.z;
            ws2f[(q*4+3)*8 + o] = v.w;
        }
    }

    // snapshot own progress counter (self-owned word: race-free; all CTAs see
    // the same value because a replay only starts after the prior one fully ends)
    if (tid == 0) s_base = *(volatile unsigned*)&g_prog[blockIdx.x];
    __syncthreads();
    const unsigned base = s_base;

    const int g4  = tid >> 6;       // splitK group 0..3 (uniform per warp-pair)
    const int pos = tid & 63;
    const int bg  = pos >> 2;       // 0..15 (4 b's each)
    const int jp  = pos & 3;        // j-pair 0..3
    const int sbg = ((bg + 4) & 7) | (bg & 8);   // sigma(bg) for A23 reads
    const int pollp = tid & (NCTA - 1);          // CTA this thread polls

    for (int s = 0; s < SS; s++) {
        const float* hp = (s == 0) ? g_h0 : (g_hs + (size_t)(s - 1) * D_H * BB);

        // ---- prefetch epilogue operands for this step ----
        float e_gir[2], e_giz[2], e_gin[2], e_hp[2];
        const float* gi0 = g_gi + (size_t)s * 64;
#pragma unroll
        for (int ii = 0; ii < 2; ii++) {
            int o  = tid + ii * 256;
            int jj = o >> 6, b = o & 63;
            int j  = j0 + jj;
            const float* gip = gi0 + (size_t)j * (SS * BB) + b;
            e_gir[ii] = gip[0];
            e_giz[ii] = gip[(size_t)D_H * SS * BB];
            e_gin[ii] = gip[(size_t)2 * D_H * SS * BB];
            e_hp[ii]  = hp[(size_t)j * 64 + b];
        }

        u64t acc[4][3];
#pragma unroll
        for (int u = 0; u < 4; u++)
#pragma unroll
            for (int g = 0; g < 3; g++) acc[u][g] = 0ull;

        // ---- stage tile 0 directly (sigma-permuted dup layout) ----
#pragma unroll
        for (int c = 0; c < 16; c++) {
            int row = wid * 16 + c;
            float2 v = *(const float2*)(hp + (size_t)row * 64 + lane * 2);
            *(float4*)(buf0 + row * 128 + dupoff) = make_float4(v.x, v.x, v.y, v.y);
        }
        __syncthreads();

        for (int t = 0; t < 8; t++) {
            // prefetch next tile into registers (hidden behind compute)
            u64t pf[16];
            if (t < 7) {
#pragma unroll
                for (int c = 0; c < 16; c++) {
                    int row = wid * 16 + c;
                    pf[c] = *(const u64t*)(hp + (size_t)((t + 1) * 128 + row) * 64 + lane * 2);
                }
            }

            const u64t* b8 = (const u64t*)((t & 1) ? buf1 : buf0);
            const u64t* w01p = ws01 + (size_t)(t * 128 + g4 * 32) * 8 + jp * 2;
            const u64t* w2p  = ws2  + (size_t)(t * 128 + g4 * 32) * 4 + jp;

            // ---- first half: kk 0..15 ----
#pragma unroll 4
            for (int kk = 0; kk < 16; kk++) {
                int kl = g4 * 32 + kk;
                ulonglong2 A01 = *(const ulonglong2*)(b8 + kl*64 + bg*2);
                ulonglong2 A23 = *(const ulonglong2*)(b8 + kl*64 + 32 + sbg*2);
                ulonglong2 W01 = *(const ulonglong2*)(w01p + kk*8);
                u64t w2v = w2p[kk*4];
                fma2(acc[0][0], A01.x, W01.x); fma2(acc[1][0], A01.y, W01.x);
                fma2(acc[2][0], A23.x, W01.x); fma2(acc[3][0], A23.y, W01.x);
                fma2(acc[0][1], A01.x, W01.y); fma2(acc[1][1], A01.y, W01.y);
                fma2(acc[2][1], A23.x, W01.y); fma2(acc[3][1], A23.y, W01.y);
                fma2(acc[0][2], A01.x, w2v);   fma2(acc[1][2], A01.y, w2v);
                fma2(acc[2][2], A23.x, w2v);   fma2(acc[3][2], A23.y, w2v);
            }

            // ---- overlapped dup-store of tile t+1 (target buffer is idle) ----
            if (t < 7) {
                float* dst = (t & 1) ? buf0 : buf1;
#pragma unroll
                for (int c = 0; c < 16; c++) {
                    int row = wid * 16 + c;
                    float2 v = up2(pf[c]);
                    *(float4*)(dst + row * 128 + dupoff) = make_float4(v.x, v.x, v.y, v.y);
                }
            }

            // ---- second half: kk 16..31 ----
#pragma unroll 4
            for (int kk = 16; kk < 32; kk++) {
                int kl = g4 * 32 + kk;
                ulonglong2 A01 = *(const ulonglong2*)(b8 + kl*64 + bg*2);
                ulonglong2 A23 = *(const ulonglong2*)(b8 + kl*64 + 32 + sbg*2);
                ulonglong2 W01 = *(const ulonglong2*)(w01p + kk*8);
                u64t w2v = w2p[kk*4];
                fma2(acc[0][0], A01.x, W01.x); fma2(acc[1][0], A01.y, W01.x);
                fma2(acc[2][0], A23.x, W01.x); fma2(acc[3][0], A23.y, W01.x);
                fma2(acc[0][1], A01.x, W01.y); fma2(acc[1][1], A01.y, W01.y);
                fma2(acc[2][1], A23.x, W01.y); fma2(acc[3][1], A23.y, W01.y);
                fma2(acc[0][2], A01.x, w2v);   fma2(acc[1][2], A01.y, w2v);
                fma2(acc[2][2], A23.x, w2v);   fma2(acc[3][2], A23.y, w2v);
            }

            if (t < 7) __syncthreads();
        }

        // ---- splitK partial sums -> red (stride 68, conflict-free) ----
#pragma unroll
        for (int u = 0; u < 4; u++) {
            int b = bg * 4 + u;
#pragma unroll
            for (int g = 0; g < 3; g++) {
                float2 p = up2(acc[u][g]);
                red[((g4*3 + g)*8 + jp*2 + 0)*REDSTRIDE + b] = p.x;
                red[((g4*3 + g)*8 + jp*2 + 1)*REDSTRIDE + b] = p.y;
            }
        }
        __syncthreads();

        // ---- gate epilogue: 512 outputs, 2 per thread, coalesced store ----
        float* hout = g_hs + (size_t)s * D_H * BB;
#pragma unroll
        for (int ii = 0; ii < 2; ii++) {
            int o  = tid + ii * 256;
            int jj = o >> 6, b = o & 63;
            int j  = j0 + jj;
            float ghr = 0.f, ghz = 0.f, ghn = 0.f;
#pragma unroll
            for (int g = 0; g < 4; g++) {
                ghr += red[((g*3 + 0)*8 + jj)*REDSTRIDE + b];
                ghz += red[((g*3 + 1)*8 + jj)*REDSTRIDE + b];
                ghn += red[((g*3 + 2)*8 + jj)*REDSTRIDE + b];
            }
            float r = 1.f / (1.f + expf(-(e_gir[ii] + ghr + b_hh[j])));
            float z = 1.f / (1.f + expf(-(e_giz[ii] + ghz + b_hh[D_H + j])));
            float n = tanhf(e_gin[ii] + r * (ghn + b_hh[2 * D_H + j]));
            hout[(size_t)j * 64 + b] = (1.f - z) * n + z * e_hp[ii];
        }

        // ---- step sync: publish own progress, wait for all CTAs ----
        __threadfence();                    // order this thread's h stores
        __syncthreads();                    // all threads' stores+fences done
        if (tid == 0)
            *(volatile unsigned*)&g_prog[blockIdx.x] = base + (unsigned)(s + 1);
        if (s < SS - 1) {
            const unsigned tgt = base + (unsigned)(s + 1);
            while (*(volatile unsigned*)&g_prog[pollp] < tgt) { }
            __syncthreads();
        }
    }
}

// ==============================================================================
// Kernel 3: fc + log_softmax (unchanged)
// ==============================================================================
__global__ __launch_bounds__(256) void fc_lsm(
    const float* __restrict__ fc_w, const float* __restrict__ fc_b,
    float* __restrict__ out)
{
    __shared__ float hst[32 * 64];     // [k][b] natural, 8 KB
    __shared__ float wst[64 * 36];     // [o][k] padded,  9 KB
    __shared__ float L  [64 * 65];     // logits, 16.25 KB

    const int tid = threadIdx.x;
    const int s   = blockIdx.x;
    const float* hs_s = g_hs + (size_t)s * D_H * BB;
    const int og = tid & 15, bg = tid >> 4;

    u64t acc[2][4];
#pragma unroll
    for (int u = 0; u < 2; u++)
#pragma unroll
        for (int v = 0; v < 4; v++) acc[u][v] = 0ull;
    u64t* hst8 = (u64t*)hst;

    for (int k0 = 0; k0 < D_H; k0 += 32) {
        __syncthreads();
#pragma unroll
        for (int i = 0; i < 2; i++) {
            int q = tid + i * 256;
            int kl = q >> 4, bq = q & 15;
            *(float4*)(hst + kl*64 + bq*4) =
                *(const float4*)(hs_s + (size_t)(k0 + kl) * 64 + bq * 4);
        }
#pragma unroll
        for (int i = 0; i < 2; i++) {
            int q = tid + i * 256;
            int o = q >> 3, kq = q & 7;
            *(float4*)(wst + o*36 + kq*4) =
                *(const float4*)(fc_w + (size_t)o * D_H + k0 + kq * 4);
        }
        __syncthreads();
#pragma unroll 4
        for (int kk = 0; kk < 32; kk++) {
            u64t h0 = hst8[kk*32 + bg*2 + 0];
            u64t h1 = hst8[kk*32 + bg*2 + 1];
#pragma unroll
            for (int v = 0; v < 4; v++) {
                u64t wd = dup64(wst[(og*4 + v)*36 + kk]);
                fma2(acc[0][v], h0, wd);
                fma2(acc[1][v], h1, wd);
            }
        }
    }

    __syncthreads();
#pragma unroll
    for (int u = 0; u < 2; u++) {
#pragma unroll
        for (int v = 0; v < 4; v++) {
            float2 p = up2(acc[u][v]);
            int o  = og * 4 + v;
            int b0 = bg * 4 + u * 2;
            float bias = fc_b[o];
            L[(b0 + 0)*65 + o] = p.x + bias;
            L[(b0 + 1)*65 + o] = p.y + bias;
        }
    }
    __syncthreads();

    const int w = tid >> 5, lane = tid & 31;
#pragma unroll
    for (int rr = 0; rr < 8; rr++) {
        int b = w * 8 + rr;
        float v0 = L[b*65 + lane], v1 = L[b*65 + 32 + lane];
        float mx = fmaxf(v0, v1);
#pragma unroll
        for (int o = 16; o > 0; o >>= 1) mx = fmaxf(mx, __shfl_xor_sync(0xffffffffu, mx, o));
        float se = expf(v0 - mx) + expf(v1 - mx);
#pragma unroll
        for (int o = 16; o > 0; o >>= 1) se += __shfl_xor_sync(0xffffffffu, se, o);
        float lse = logf(se) + mx;
        float* op = out + ((size_t)b * SS + s) * D_OUT;
        op[lane]      = v0 - lse;
        op[lane + 32] = v1 - lse;
    }
}

// ==============================================================================
extern "C" void kernel_launch(void* const* d_in, const int* in_sizes, int n_in,
                              void* d_out, int out_size)
{
    (void)in_sizes; (void)n_in; (void)out_size;
    const int*   x    = (const int*)  d_in[0];
    const float* emb  = (const float*)d_in[1];
    const float* w_ih = (const float*)d_in[2];
    const float* w_hh = (const float*)d_in[3];
    const float* b_ih = (const float*)d_in[4];
    const float* b_hh = (const float*)d_in[5];
    const float* fc_w = (const float*)d_in[6];
    const float* fc_b = (const float*)d_in[7];
    float* out = (float*)d_out;

    const int rec_smem = (24576 + 16384 + 16384) * 4;   // 224 KB
    cudaFuncSetAttribute(gru_persistent,
                         cudaFuncAttributeMaxDynamicSharedMemorySize, rec_smem);

    gi_gemm<<<dim3((SS * BB) / 128, D3H / 128), 256>>>(x, emb, w_ih, b_ih);
    gru_persistent<<<NCTA, 256, rec_smem>>>(w_hh, b_hh);
    fc_lsm<<<SS, 256>>>(fc_w, fc_b, out);
}

// round 8
// speedup vs baseline: 1.3045x; 1.3045x over previous
#include <cuda_runtime.h>
#include <math.h>

#define VOCAB 32000
#define D_IN  512
#define D_H   1024
#define D3H   3072
#define D_OUT 64
#define BB    64
#define SS    256
#define NCTA  128

typedef unsigned long long u64t;

// ---------------- scratch (static device globals; zero-init at load) ----------
// gi transposed: [3H rows][S*B cols]  (row = gate*1024+j, col = s*64+b)
__device__ float g_gi[(size_t)D3H * SS * BB];
// h transposed: [s][j][b]
__device__ float g_hs[(size_t)SS * D_H * BB];
__device__ float g_h0[D_H * BB];                // all-zero h(-1), never written

// ---------------- grid barrier state (R3/R6 proven protocol) -------------------
__device__ unsigned g_cnt = 0;
__device__ volatile unsigned g_flag = 0;        // cumulative barriers passed (monotonic)

// ---------------- f32x2 helpers ------------------------------------------------
__device__ __forceinline__ void fma2(u64t& c, u64t a, u64t b) {
    asm("fma.rn.f32x2 %0, %1, %2, %0;" : "+l"(c) : "l"(a), "l"(b));
}
__device__ __forceinline__ float2 up2(u64t v) {
    float2 r;
    asm("mov.b64 {%0, %1}, %2;" : "=f"(r.x), "=f"(r.y) : "l"(v));
    return r;
}
__device__ __forceinline__ u64t dup64(float w) {
    u64t r;
    asm("mov.b64 %0, {%1, %1};" : "=l"(r) : "f"(w));
    return r;
}

// ==============================================================================
// Kernel 1: g_gi[n][m] = sum_d w_ih[n][d] * emb[x(m)][d] + b_ih[n]   (unchanged)
// ==============================================================================
__global__ __launch_bounds__(256) void gi_gemm(
    const int* __restrict__ x, const float* __restrict__ emb,
    const float* __restrict__ w_ih, const float* __restrict__ b_ih)
{
    __shared__ float2 As2[16][128];   // 16 KB (w_ih side, duplicated)
    __shared__ float  Bs [16][128];   //  8 KB (gathered emb side)

    const int tid   = threadIdx.x;
    const int m_blk = blockIdx.y * 128;    // w_ih rows
    const int n_blk = blockIdx.x * 128;    // token cols

    const float* aptr[2]; int arow[2], akq[2];
    const float* bptr[2];
#pragma unroll
    for (int t = 0; t < 2; t++) {
        int i   = tid + t * 256;            // 0..511
        arow[t] = i >> 2;                   // 0..127
        akq[t]  = (i & 3) * 4;
        aptr[t] = w_ih + (size_t)(m_blk + arow[t]) * D_IN;
        int n = n_blk + arow[t];
        int s = n >> 6, b = n & 63;         // n = s*B + b
        int tok = x[b * SS + s];
        bptr[t] = emb + (size_t)tok * D_IN;
    }

    u64t c2[8][4];
#pragma unroll
    for (int i = 0; i < 8; i++)
#pragma unroll
        for (int j = 0; j < 4; j++) c2[i][j] = 0ull;

    const int ty = tid >> 4, tx = tid & 15;

    for (int kt = 0; kt < D_IN; kt += 16) {
#pragma unroll
        for (int t = 0; t < 2; t++) {
            float4 v = *(const float4*)(aptr[t] + kt + akq[t]);
            As2[akq[t]+0][arow[t]] = make_float2(v.x, v.x);
            As2[akq[t]+1][arow[t]] = make_float2(v.y, v.y);
            As2[akq[t]+2][arow[t]] = make_float2(v.z, v.z);
            As2[akq[t]+3][arow[t]] = make_float2(v.w, v.w);
            float4 w = *(const float4*)(bptr[t] + kt + akq[t]);
            Bs[akq[t]+0][arow[t]] = w.x;
            Bs[akq[t]+1][arow[t]] = w.y;
            Bs[akq[t]+2][arow[t]] = w.z;
            Bs[akq[t]+3][arow[t]] = w.w;
        }
        __syncthreads();
#pragma unroll
        for (int k = 0; k < 16; k++) {
            u64t ad[8], bb[4];
#pragma unroll
            for (int i = 0; i < 4; i++) {
                ad[i]     = *(const u64t*)&As2[k][ty*4 + i];
                ad[i + 4] = *(const u64t*)&As2[k][64 + ty*4 + i];
            }
            bb[0] = *(const u64t*)&Bs[k][tx*4];
            bb[1] = *(const u64t*)&Bs[k][tx*4 + 2];
            bb[2] = *(const u64t*)&Bs[k][64 + tx*4];
            bb[3] = *(const u64t*)&Bs[k][64 + tx*4 + 2];
#pragma unroll
            for (int i = 0; i < 8; i++)
#pragma unroll
                for (int j = 0; j < 4; j++)
                    fma2(c2[i][j], ad[i], bb[j]);
        }
        __syncthreads();
    }

#pragma unroll
    for (int i = 0; i < 8; i++) {
        int mi = (i < 4) ? (ty*4 + i) : (64 + ty*4 + (i - 4));
        size_t m = (size_t)(m_blk + mi);
        float bih = b_ih[m];
#pragma unroll
        for (int j = 0; j < 4; j++) {
            int nj = (j < 2) ? (tx*4 + j*2) : (64 + tx*4 + (j - 2)*2);
            int n  = n_blk + nj;
            float2 v = up2(c2[i][j]);
            v.x += bih;
            v.y += bih;
            *(float2*)(g_gi + m * (SS * BB) + n) = v;
        }
    }
}

// ==============================================================================
// Kernel 2: PERSISTENT GRU. 128 CTAs x 512 threads, 1 CTA/SM (4 warps/SMSP).
// splitK-8: each 64-thread group covers 16 k's per 128-k tile.
// Conflict-free SMEM (sigma-permuted dup rows, split w layout),
// R6-proven central grid barrier.
// ==============================================================================
#define REDSTRIDE 68

__global__ void __launch_bounds__(512, 1) gru_persistent(
    const float* __restrict__ w_hh, const float* __restrict__ b_hh)
{
    extern __shared__ float smem[];
    float* ws01f = smem;                      // [1024][16]  (g0,g1 pairs) 64 KB
    float* ws2f  = smem + 16384;              // [1024][8]   (g2 pairs)    32 KB
    float* buf0  = smem + 24576;              // [128][128] dup            64 KB
    float* buf1  = smem + 24576 + 16384;      // [128][128] dup            64 KB
    float* red   = buf0;                      // [192][68]                 52 KB (aliases buf0)
    u64t* ws01 = (u64t*)ws01f;
    u64t* ws2  = (u64t*)ws2f;

    const int tid  = threadIdx.x;
    const int j0   = blockIdx.x * 8;
    const int wid  = tid >> 5;
    const int lane = tid & 31;
    // dup-store float offset within a 128-float dup row (sigma-permuted):
    const int dhalf  = lane >> 1;
    const int sig_l  = ((dhalf + 4) & 7) | (dhalf & 8);
    const int dupoff = (lane & 1) ? (64 + 4 * sig_l) : (4 * dhalf);

    // ---- preload weight slice into split layout ----
    for (int idx = tid; idx < 24 * 256; idx += 512) {
        int r = idx >> 8;            // 0..23
        int q = idx & 255;           // k quad
        int g = r >> 3, jj = r & 7;
        int jp = jj >> 1, e = jj & 1;
        float4 v = *(const float4*)(w_hh + (size_t)(g * D_H + j0 + jj) * D_H + q * 4);
        if (g < 2) {
            int o = 4 * jp + 2 * g + e;
            ws01f[(q*4+0)*16 + o] = v.x;
            ws01f[(q*4+1)*16 + o] = v.y;
            ws01f[(q*4+2)*16 + o] = v.z;
            ws01f[(q*4+3)*16 + o] = v.w;
        } else {
            int o = 2 * jp + e;
            ws2f[(q*4+0)*8 + o] = v.x;
            ws2f[(q*4+1)*8 + o] = v.y;
            ws2f[(q*4+2)*8 + o] = v.z;
            ws2f[(q*4+3)*8 + o] = v.w;
        }
    }

    unsigned base = 0;
    if (tid == 0) base = g_flag;    // safe: flag can't advance until all CTAs arrive
    __syncthreads();

    const int g8  = tid >> 6;       // splitK group 0..7 (uniform per warp-pair)
    const int pos = tid & 63;
    const int bg  = pos >> 2;       // 0..15 (4 b's each)
    const int jp  = pos & 3;        // j-pair 0..3
    const int sbg = ((bg + 4) & 7) | (bg & 8);   // sigma(bg) for A23 reads

    for (int s = 0; s < SS; s++) {
        const float* hp = (s == 0) ? g_h0 : (g_hs + (size_t)(s - 1) * D_H * BB);

        // ---- prefetch epilogue operands for this step (1 output/thread) ----
        const int ejj = tid >> 6, eb = tid & 63;
        const int ej  = j0 + ejj;
        const float* gi0 = g_gi + (size_t)s * 64;
        const float* gip = gi0 + (size_t)ej * (SS * BB) + eb;
        float e_gir = gip[0];
        float e_giz = gip[(size_t)D_H * SS * BB];
        float e_gin = gip[(size_t)2 * D_H * SS * BB];
        float e_hp  = hp[(size_t)ej * 64 + eb];

        u64t acc[4][3];
#pragma unroll
        for (int u = 0; u < 4; u++)
#pragma unroll
            for (int g = 0; g < 3; g++) acc[u][g] = 0ull;

        // ---- stage tile 0 directly (16 warps x 8 rows) ----
#pragma unroll
        for (int c = 0; c < 8; c++) {
            int row = wid * 8 + c;
            float2 v = *(const float2*)(hp + (size_t)row * 64 + lane * 2);
            *(float4*)(buf0 + row * 128 + dupoff) = make_float4(v.x, v.x, v.y, v.y);
        }
        __syncthreads();

        for (int t = 0; t < 8; t++) {
            // prefetch next tile into registers (hidden behind compute)
            u64t pf[8];
            if (t < 7) {
#pragma unroll
                for (int c = 0; c < 8; c++) {
                    int row = wid * 8 + c;
                    pf[c] = *(const u64t*)(hp + (size_t)((t + 1) * 128 + row) * 64 + lane * 2);
                }
            }

            // compute tile t: this group's 16 k's
            const u64t* b8 = (const u64t*)((t & 1) ? buf1 : buf0);
            const u64t* w01p = ws01 + (size_t)(t * 128 + g8 * 16) * 8 + jp * 2;
            const u64t* w2p  = ws2  + (size_t)(t * 128 + g8 * 16) * 4 + jp;
#pragma unroll 4
            for (int kk = 0; kk < 16; kk++) {
                int kl = g8 * 16 + kk;
                ulonglong2 A01 = *(const ulonglong2*)(b8 + kl*64 + bg*2);
                ulonglong2 A23 = *(const ulonglong2*)(b8 + kl*64 + 32 + sbg*2);
                ulonglong2 W01 = *(const ulonglong2*)(w01p + kk*8);
                u64t w2v = w2p[kk*4];
                fma2(acc[0][0], A01.x, W01.x); fma2(acc[1][0], A01.y, W01.x);
                fma2(acc[2][0], A23.x, W01.x); fma2(acc[3][0], A23.y, W01.x);
                fma2(acc[0][1], A01.x, W01.y); fma2(acc[1][1], A01.y, W01.y);
                fma2(acc[2][1], A23.x, W01.y); fma2(acc[3][1], A23.y, W01.y);
                fma2(acc[0][2], A01.x, w2v);   fma2(acc[1][2], A01.y, w2v);
                fma2(acc[2][2], A23.x, w2v);   fma2(acc[3][2], A23.y, w2v);
            }

            if (t < 7) {
                float* dst = (t & 1) ? buf0 : buf1;     // the buffer NOT being read
#pragma unroll
                for (int c = 0; c < 8; c++) {
                    int row = wid * 8 + c;
                    float2 v = up2(pf[c]);
                    *(float4*)(dst + row * 128 + dupoff) = make_float4(v.x, v.x, v.y, v.y);
                }
                __syncthreads();
            }
        }

        // ---- splitK partial sums -> red [192][68] (aliases buf0; t=7 read buf1)
#pragma unroll
        for (int u = 0; u < 4; u++) {
            int b = bg * 4 + u;
#pragma unroll
            for (int g = 0; g < 3; g++) {
                float2 p = up2(acc[u][g]);
                red[((g8*3 + g)*8 + jp*2 + 0)*REDSTRIDE + b] = p.x;
                red[((g8*3 + g)*8 + jp*2 + 1)*REDSTRIDE + b] = p.y;
            }
        }
        __syncthreads();

        // ---- gate epilogue: 512 outputs, 1 per thread, coalesced store ----
        float* hout = g_hs + (size_t)s * D_H * BB;
        {
            float ghr = 0.f, ghz = 0.f, ghn = 0.f;
#pragma unroll
            for (int g = 0; g < 8; g++) {
                ghr += red[((g*3 + 0)*8 + ejj)*REDSTRIDE + eb];
                ghz += red[((g*3 + 1)*8 + ejj)*REDSTRIDE + eb];
                ghn += red[((g*3 + 2)*8 + ejj)*REDSTRIDE + eb];
            }
            float r = 1.f / (1.f + expf(-(e_gir + ghr + b_hh[ej])));
            float z = 1.f / (1.f + expf(-(e_giz + ghz + b_hh[D_H + ej])));
            float n = tanhf(e_gin + r * (ghn + b_hh[2 * D_H + ej]));
            hout[(size_t)ej * 64 + eb] = (1.f - z) * n + z * e_hp;
        }

        // ---- grid barrier (R6 proven: count + monotonic flag release) ----
        __syncthreads();
        if (tid == 0) {
            __threadfence();
            unsigned target = base + (unsigned)(s + 1);
            unsigned old = atomicAdd(&g_cnt, 1u);
            if (old == NCTA - 1) {
                atomicExch(&g_cnt, 0u);
                __threadfence();
                atomicExch((unsigned*)&g_flag, target);
            } else {
                while (g_flag < target) { }
            }
            __threadfence();
        }
        __syncthreads();
    }
}

// ==============================================================================
// Kernel 3: fc + log_softmax (unchanged)
// ==============================================================================
__global__ __launch_bounds__(256) void fc_lsm(
    const float* __restrict__ fc_w, const float* __restrict__ fc_b,
    float* __restrict__ out)
{
    __shared__ float hst[32 * 64];     // [k][b] natural, 8 KB
    __shared__ float wst[64 * 36];     // [o][k] padded,  9 KB
    __shared__ float L  [64 * 65];     // logits, 16.25 KB

    const int tid = threadIdx.x;
    const int s   = blockIdx.x;
    const float* hs_s = g_hs + (size_t)s * D_H * BB;
    const int og = tid & 15, bg = tid >> 4;

    u64t acc[2][4];
#pragma unroll
    for (int u = 0; u < 2; u++)
#pragma unroll
        for (int v = 0; v < 4; v++) acc[u][v] = 0ull;
    u64t* hst8 = (u64t*)hst;

    for (int k0 = 0; k0 < D_H; k0 += 32) {
        __syncthreads();
#pragma unroll
        for (int i = 0; i < 2; i++) {
            int q = tid + i * 256;
            int kl = q >> 4, bq = q & 15;
            *(float4*)(hst + kl*64 + bq*4) =
                *(const float4*)(hs_s + (size_t)(k0 + kl) * 64 + bq * 4);
        }
#pragma unroll
        for (int i = 0; i < 2; i++) {
            int q = tid + i * 256;
            int o = q >> 3, kq = q & 7;
            *(float4*)(wst + o*36 + kq*4) =
                *(const float4*)(fc_w + (size_t)o * D_H + k0 + kq * 4);
        }
        __syncthreads();
#pragma unroll 4
        for (int kk = 0; kk < 32; kk++) {
            u64t h0 = hst8[kk*32 + bg*2 + 0];
            u64t h1 = hst8[kk*32 + bg*2 + 1];
#pragma unroll
            for (int v = 0; v < 4; v++) {
                u64t wd = dup64(wst[(og*4 + v)*36 + kk]);
                fma2(acc[0][v], h0, wd);
                fma2(acc[1][v], h1, wd);
            }
        }
    }

    __syncthreads();
#pragma unroll
    for (int u = 0; u < 2; u++) {
#pragma unroll
        for (int v = 0; v < 4; v++) {
            float2 p = up2(acc[u][v]);
            int o  = og * 4 + v;
            int b0 = bg * 4 + u * 2;
            float bias = fc_b[o];
            L[(b0 + 0)*65 + o] = p.x + bias;
            L[(b0 + 1)*65 + o] = p.y + bias;
        }
    }
    __syncthreads();

    const int w = tid >> 5, lane = tid & 31;
#pragma unroll
    for (int rr = 0; rr < 8; rr++) {
        int b = w * 8 + rr;
        float v0 = L[b*65 + lane], v1 = L[b*65 + 32 + lane];
        float mx = fmaxf(v0, v1);
#pragma unroll
        for (int o = 16; o > 0; o >>= 1) mx = fmaxf(mx, __shfl_xor_sync(0xffffffffu, mx, o));
        float se = expf(v0 - mx) + expf(v1 - mx);
#pragma unroll
        for (int o = 16; o > 0; o >>= 1) se += __shfl_xor_sync(0xffffffffu, se, o);
        float lse = logf(se) + mx;
        float* op = out + ((size_t)b * SS + s) * D_OUT;
        op[lane]      = v0 - lse;
        op[lane + 32] = v1 - lse;
    }
}

// ==============================================================================
extern "C" void kernel_launch(void* const* d_in, const int* in_sizes, int n_in,
                              void* d_out, int out_size)
{
    (void)in_sizes; (void)n_in; (void)out_size;
    const int*   x    = (const int*)  d_in[0];
    const float* emb  = (const float*)d_in[1];
    const float* w_ih = (const float*)d_in[2];
    const float* w_hh = (const float*)d_in[3];
    const float* b_ih = (const float*)d_in[4];
    const float* b_hh = (const float*)d_in[5];
    const float* fc_w = (const float*)d_in[6];
    const float* fc_b = (const float*)d_in[7];
    float* out = (float*)d_out;

    const int rec_smem = (24576 + 16384 + 16384) * 4;   // 224 KB
    cudaFuncSetAttribute(gru_persistent,
                         cudaFuncAttributeMaxDynamicSharedMemorySize, rec_smem);

    gi_gemm<<<dim3((SS * BB) / 128, D3H / 128), 256>>>(x, emb, w_ih, b_ih);
    gru_persistent<<<NCTA, 512, rec_smem>>>(w_hh, b_hh);
    fc_lsm<<<SS, 256>>>(fc_w, fc_b, out);
}

// round 10
// speedup vs baseline: 1.9347x; 1.4831x over previous
#include <cuda_runtime.h>
#include <cuda_fp16.h>
#include <math.h>

#define VOCAB 32000
#define D_IN  512
#define D_H   1024
#define D3H   3072
#define D_OUT 64
#define BB    64
#define SS    256
#define NCTA  128

typedef unsigned long long u64t;
typedef unsigned int u32t;

// ---------------- scratch (static device globals; zero-init at load) ----------
// gi transposed: [3H rows][S*B cols]  (row = gate*1024+j, col = s*64+b)
__device__ float g_gi[(size_t)D3H * SS * BB];
// h fp32 transposed: [s][j][b]  (exact, consumed by fc and z-path)
__device__ float g_hs[(size_t)SS * D_H * BB];
__device__ float g_h0[D_H * BB];                // all-zero h(-1), never written
// fp16 hi/lo split of h for the HMMA recurrence: [j][b]
__device__ unsigned short g_hh[D_H * BB];
__device__ unsigned short g_hl[D_H * BB];
__device__ unsigned short g_hbz[D_H * BB];      // zeros (step 0)

// ---------------- grid barrier state (R3/R6/R8 proven protocol) ----------------
__device__ unsigned g_cnt = 0;
__device__ volatile unsigned g_flag = 0;        // cumulative barriers passed (monotonic)

// ---------------- f32x2 helpers (gi/fc kernels) --------------------------------
__device__ __forceinline__ void fma2(u64t& c, u64t a, u64t b) {
    asm("fma.rn.f32x2 %0, %1, %2, %0;" : "+l"(c) : "l"(a), "l"(b));
}
__device__ __forceinline__ float2 up2(u64t v) {
    float2 r;
    asm("mov.b64 {%0, %1}, %2;" : "=f"(r.x), "=f"(r.y) : "l"(v));
    return r;
}
__device__ __forceinline__ u64t dup64(float w) {
    u64t r;
    asm("mov.b64 %0, {%1, %1};" : "=l"(r) : "f"(w));
    return r;
}
__device__ __forceinline__ u32t prmt(u32t a, u32t b, u32t s) {
    u32t d;
    asm("prmt.b32 %0, %1, %2, %3;" : "=r"(d) : "r"(a), "r"(b), "r"(s));
    return d;
}
// mma.sync m16n8k16 f16 -> f32 (sm_80 baseline PTX; compiles for base sm_103)
__device__ __forceinline__ void mma16816(float* d, u32t a0, u32t a1, u32t a2, u32t a3,
                                         u32t b0, u32t b1) {
    asm volatile(
        "mma.sync.aligned.m16n8k16.row.col.f32.f16.f16.f32 "
        "{%0,%1,%2,%3}, {%4,%5,%6,%7}, {%8,%9}, {%0,%1,%2,%3};"
        : "+f"(d[0]), "+f"(d[1]), "+f"(d[2]), "+f"(d[3])
        : "r"(a0), "r"(a1), "r"(a2), "r"(a3), "r"(b0), "r"(b1));
}

// ==============================================================================
// Kernel 1: g_gi[n][m] = sum_d w_ih[n][d] * emb[x(m)][d] + b_ih[n]   (unchanged)
// ==============================================================================
__global__ __launch_bounds__(256) void gi_gemm(
    const int* __restrict__ x, const float* __restrict__ emb,
    const float* __restrict__ w_ih, const float* __restrict__ b_ih)
{
    __shared__ float2 As2[16][128];
    __shared__ float  Bs [16][128];

    const int tid   = threadIdx.x;
    const int m_blk = blockIdx.y * 128;
    const int n_blk = blockIdx.x * 128;

    const float* aptr[2]; int arow[2], akq[2];
    const float* bptr[2];
#pragma unroll
    for (int t = 0; t < 2; t++) {
        int i   = tid + t * 256;
        arow[t] = i >> 2;
        akq[t]  = (i & 3) * 4;
        aptr[t] = w_ih + (size_t)(m_blk + arow[t]) * D_IN;
        int n = n_blk + arow[t];
        int s = n >> 6, b = n & 63;
        int tok = x[b * SS + s];
        bptr[t] = emb + (size_t)tok * D_IN;
    }

    u64t c2[8][4];
#pragma unroll
    for (int i = 0; i < 8; i++)
#pragma unroll
        for (int j = 0; j < 4; j++) c2[i][j] = 0ull;

    const int ty = tid >> 4, tx = tid & 15;

    for (int kt = 0; kt < D_IN; kt += 16) {
#pragma unroll
        for (int t = 0; t < 2; t++) {
            float4 v = *(const float4*)(aptr[t] + kt + akq[t]);
            As2[akq[t]+0][arow[t]] = make_float2(v.x, v.x);
            As2[akq[t]+1][arow[t]] = make_float2(v.y, v.y);
            As2[akq[t]+2][arow[t]] = make_float2(v.z, v.z);
            As2[akq[t]+3][arow[t]] = make_float2(v.w, v.w);
            float4 w = *(const float4*)(bptr[t] + kt + akq[t]);
            Bs[akq[t]+0][arow[t]] = w.x;
            Bs[akq[t]+1][arow[t]] = w.y;
            Bs[akq[t]+2][arow[t]] = w.z;
            Bs[akq[t]+3][arow[t]] = w.w;
        }
        __syncthreads();
#pragma unroll
        for (int k = 0; k < 16; k++) {
            u64t ad[8], bb[4];
#pragma unroll
            for (int i = 0; i < 4; i++) {
                ad[i]     = *(const u64t*)&As2[k][ty*4 + i];
                ad[i + 4] = *(const u64t*)&As2[k][64 + ty*4 + i];
            }
            bb[0] = *(const u64t*)&Bs[k][tx*4];
            bb[1] = *(const u64t*)&Bs[k][tx*4 + 2];
            bb[2] = *(const u64t*)&Bs[k][64 + tx*4];
            bb[3] = *(const u64t*)&Bs[k][64 + tx*4 + 2];
#pragma unroll
            for (int i = 0; i < 8; i++)
#pragma unroll
                for (int j = 0; j < 4; j++)
                    fma2(c2[i][j], ad[i], bb[j]);
        }
        __syncthreads();
    }

#pragma unroll
    for (int i = 0; i < 8; i++) {
        int mi = (i < 4) ? (ty*4 + i) : (64 + ty*4 + (i - 4));
        size_t m = (size_t)(m_blk + mi);
        float bih = b_ih[m];
#pragma unroll
        for (int j = 0; j < 4; j++) {
            int nj = (j < 2) ? (tx*4 + j*2) : (64 + tx*4 + (j - 2)*2);
            int n  = n_blk + nj;
            float2 v = up2(c2[i][j]);
            v.x += bih;
            v.y += bih;
            *(float2*)(g_gi + m * (SS * BB) + n) = v;
        }
    }
}

// ==============================================================================
// Kernel 2: PERSISTENT GRU, HMMA recurrence (mma.sync m16n8k16 fp16 hi/lo).
// 128 CTAs x 512 threads, 1 CTA/SM. 16 warps = 4 M-tiles x splitK-4.
// W fp16 hi/lo resident in SMEM [k2][24]; h streamed per 128-k chunk into
// [k2][72] fp16x2 (k-interleaved via PRMT). R8-proven grid barrier.
// ==============================================================================
// SMEM word offsets
#define WH_O   0          // [512 k2][24] fp16x2 hi : 12288 words
#define WL_O   12288      // lo                     : 12288 words
#define HB_O   24576      // 2 buf x (hi 4608 + lo 4608) = 18432 words
#define RED_O  43008      // [4][64][30] float = 7680 words
#define SM_WORDS 50688    // 202752 bytes

__global__ void __launch_bounds__(512, 1) gru_persistent(
    const float* __restrict__ w_hh, const float* __restrict__ b_hh)
{
    extern __shared__ u32t smw[];
    float* redf = (float*)(smw + RED_O);

    const int tid  = threadIdx.x;
    const int j0   = blockIdx.x * 8;
    const int wid  = tid >> 5;
    const int lane = tid & 31;

    // ---- one-time: W slice -> fp16 hi/lo, layout [k2 global][24 n] ----
    {
        int k2 = tid;                       // 0..511
#pragma unroll 1
        for (int n = 0; n < 24; n++) {
            int g = n >> 3, jj = n & 7;
            float2 wv = *(const float2*)(w_hh + (size_t)(g * D_H + j0 + jj) * D_H + k2 * 2);
            __half h0 = __float2half_rn(wv.x);
            __half l0 = __float2half_rn(wv.x - __half2float(h0));
            __half h1 = __float2half_rn(wv.y);
            __half l1 = __float2half_rn(wv.y - __half2float(h1));
            smw[WH_O + k2 * 24 + n] = (u32t)__half_as_ushort(h0) | ((u32t)__half_as_ushort(h1) << 16);
            smw[WL_O + k2 * 24 + n] = (u32t)__half_as_ushort(l0) | ((u32t)__half_as_ushort(l1) << 16);
        }
    }

    unsigned base = 0;
    if (tid == 0) base = g_flag;    // proven-safe snapshot
    __syncthreads();

    const int mt = wid & 3;         // M tile (16 rows)
    const int ks = wid >> 2;        // splitK group 0..3
    const int mrow = mt * 16 + (lane >> 2);
    const int ncol = lane >> 2;
    // epilogue output (1 per thread)
    const int ejj = tid >> 6, eb = tid & 63;
    const int ej  = j0 + ejj;
    const float bhr = b_hh[ej], bhz = b_hh[D_H + ej], bhn = b_hh[2 * D_H + ej];

    for (int s = 0; s < SS; s++) {
        const float* hp32 = (s == 0) ? g_h0 : (g_hs + (size_t)(s - 1) * D_H * BB);
        const unsigned short* hbh = (s == 0) ? g_hbz : g_hh;
        const unsigned short* hbl = (s == 0) ? g_hbz : g_hl;

        // ---- epilogue operand prefetch ----
        const float* gip = g_gi + (size_t)s * 64 + (size_t)ej * (SS * BB) + eb;
        float e_gir = gip[0];
        float e_giz = gip[(size_t)D_H * SS * BB];
        float e_gin = gip[(size_t)2 * D_H * SS * BB];
        float e_hp  = hp32[(size_t)ej * 64 + eb];

        float d[3][4];
#pragma unroll
        for (int nt = 0; nt < 3; nt++)
#pragma unroll
            for (int u = 0; u < 4; u++) d[nt][u] = 0.f;

        // ---- stage chunk 0 into buf 0 ----
#pragma unroll
        for (int uu = 0; uu < 2; uu++) {
            int u = tid + uu * 512;
            int half = u >> 9, r = u & 511, k2 = r >> 3, bo = r & 7;
            const unsigned short* src = (half ? hbl : hbh) + (size_t)(2 * k2) * 64 + bo * 8;
            uint4 r0 = *(const uint4*)src;
            uint4 r1 = *(const uint4*)(src + 64);
            u32t* dst = smw + HB_O + half * 4608 + k2 * 72 + bo * 8;
            dst[0] = prmt(r0.x, r1.x, 0x5410); dst[1] = prmt(r0.x, r1.x, 0x7632);
            dst[2] = prmt(r0.y, r1.y, 0x5410); dst[3] = prmt(r0.y, r1.y, 0x7632);
            dst[4] = prmt(r0.z, r1.z, 0x5410); dst[5] = prmt(r0.z, r1.z, 0x7632);
            dst[6] = prmt(r0.w, r1.w, 0x5410); dst[7] = prmt(r0.w, r1.w, 0x7632);
        }
        __syncthreads();

        for (int g = 0; g < 8; g++) {
            // prefetch next chunk (global -> regs)
            uint4 pr[2][2];
            if (g < 7) {
#pragma unroll
                for (int uu = 0; uu < 2; uu++) {
                    int u = tid + uu * 512;
                    int half = u >> 9, r = u & 511, k2 = r >> 3, bo = r & 7;
                    const unsigned short* src = (half ? hbl : hbh)
                        + (size_t)((g + 1) * 128 + 2 * k2) * 64 + bo * 8;
                    pr[uu][0] = *(const uint4*)src;
                    pr[uu][1] = *(const uint4*)(src + 64);
                }
            }

            // compute chunk g: this warp's 2 ktiles (tl = ks, ks+4)
            const u32t* hb = smw + HB_O + (g & 1) * 9216;
#pragma unroll
            for (int it = 0; it < 2; it++) {
                int tl = ks + it * 4;
                int ka = tl * 8 + (lane & 3);
                u32t ah0 = hb[ka * 72 + mrow];
                u32t ah1 = hb[ka * 72 + mrow + 8];
                u32t ah2 = hb[(ka + 4) * 72 + mrow];
                u32t ah3 = hb[(ka + 4) * 72 + mrow + 8];
                u32t al0 = hb[4608 + ka * 72 + mrow];
                u32t al1 = hb[4608 + ka * 72 + mrow + 8];
                u32t al2 = hb[4608 + (ka + 4) * 72 + mrow];
                u32t al3 = hb[4608 + (ka + 4) * 72 + mrow + 8];
                int kw = (g * 64 + ka) * 24 + ncol;
#pragma unroll
                for (int nt = 0; nt < 3; nt++) {
                    u32t bh0 = smw[WH_O + kw + nt * 8];
                    u32t bh1 = smw[WH_O + kw + 96 + nt * 8];
                    u32t bl0 = smw[WL_O + kw + nt * 8];
                    u32t bl1 = smw[WL_O + kw + 96 + nt * 8];
                    mma16816(d[nt], ah0, ah1, ah2, ah3, bh0, bh1);
                    mma16816(d[nt], ah0, ah1, ah2, ah3, bl0, bl1);
                    mma16816(d[nt], al0, al1, al2, al3, bh0, bh1);
                }
            }

            if (g < 7) {
                // interleave + store prefetched chunk into the idle buffer
                u32t* bufbase = smw + HB_O + ((g + 1) & 1) * 9216;
#pragma unroll
                for (int uu = 0; uu < 2; uu++) {
                    int u = tid + uu * 512;
                    int half = u >> 9, r = u & 511, k2 = r >> 3, bo = r & 7;
                    u32t* dst = bufbase + half * 4608 + k2 * 72 + bo * 8;
                    uint4 r0 = pr[uu][0], r1 = pr[uu][1];
                    dst[0] = prmt(r0.x, r1.x, 0x5410); dst[1] = prmt(r0.x, r1.x, 0x7632);
                    dst[2] = prmt(r0.y, r1.y, 0x5410); dst[3] = prmt(r0.y, r1.y, 0x7632);
                    dst[4] = prmt(r0.z, r1.z, 0x5410); dst[5] = prmt(r0.z, r1.z, 0x7632);
                    dst[6] = prmt(r0.w, r1.w, 0x5410); dst[7] = prmt(r0.w, r1.w, 0x7632);
                }
                __syncthreads();
            }
        }

        // ---- D fragments -> red [4 ks][64 m][30 n-pad] ----
#pragma unroll
        for (int nt = 0; nt < 3; nt++) {
            int rb = (ks * 64 + mt * 16 + (lane >> 2)) * 30 + nt * 8 + 2 * (lane & 3);
            *(float2*)&redf[rb]       = make_float2(d[nt][0], d[nt][1]);
            *(float2*)&redf[rb + 240] = make_float2(d[nt][2], d[nt][3]);
        }
        __syncthreads();

        // ---- gate epilogue: 512 outputs, 1 per thread ----
        {
            float ghr = 0.f, ghz = 0.f, ghn = 0.f;
#pragma unroll
            for (int k = 0; k < 4; k++) {
                int rb = (k * 64 + eb) * 30;
                ghr += redf[rb + ejj];
                ghz += redf[rb + 8 + ejj];
                ghn += redf[rb + 16 + ejj];
            }
            float r = 1.f / (1.f + expf(-(e_gir + ghr + bhr)));
            float z = 1.f / (1.f + expf(-(e_giz + ghz + bhz)));
            float n = tanhf(e_gin + r * (ghn + bhn));
            float h = (1.f - z) * n + z * e_hp;
            g_hs[(size_t)s * D_H * BB + (size_t)ej * 64 + eb] = h;
            __half hh = __float2half_rn(h);
            __half hl = __float2half_rn(h - __half2float(hh));
            g_hh[ej * 64 + eb] = __half_as_ushort(hh);
            g_hl[ej * 64 + eb] = __half_as_ushort(hl);
        }

        // ---- grid barrier (R8 proven: count + monotonic flag release) ----
        __syncthreads();
        if (tid == 0) {
            __threadfence();
            unsigned target = base + (unsigned)(s + 1);
            unsigned old = atomicAdd(&g_cnt, 1u);
            if (old == NCTA - 1) {
                atomicExch(&g_cnt, 0u);
                __threadfence();
                atomicExch((unsigned*)&g_flag, target);
            } else {
                while (g_flag < target) { }
            }
            __threadfence();
        }
        __syncthreads();
    }
}

// ==============================================================================
// Kernel 3: fc + log_softmax (unchanged)
// ==============================================================================
__global__ __launch_bounds__(256) void fc_lsm(
    const float* __restrict__ fc_w, const float* __restrict__ fc_b,
    float* __restrict__ out)
{
    __shared__ float hst[32 * 64];
    __shared__ float wst[64 * 36];
    __shared__ float L  [64 * 65];

    const int tid = threadIdx.x;
    const int s   = blockIdx.x;
    const float* hs_s = g_hs + (size_t)s * D_H * BB;
    const int og = tid & 15, bg = tid >> 4;

    u64t acc[2][4];
#pragma unroll
    for (int u = 0; u < 2; u++)
#pragma unroll
        for (int v = 0; v < 4; v++) acc[u][v] = 0ull;
    u64t* hst8 = (u64t*)hst;

    for (int k0 = 0; k0 < D_H; k0 += 32) {
        __syncthreads();
#pragma unroll
        for (int i = 0; i < 2; i++) {
            int q = tid + i * 256;
            int kl = q >> 4, bq = q & 15;
            *(float4*)(hst + kl*64 + bq*4) =
                *(const float4*)(hs_s + (size_t)(k0 + kl) * 64 + bq * 4);
        }
#pragma unroll
        for (int i = 0; i < 2; i++) {
            int q = tid + i * 256;
            int o = q >> 3, kq = q & 7;
            *(float4*)(wst + o*36 + kq*4) =
                *(const float4*)(fc_w + (size_t)o * D_H + k0 + kq * 4);
        }
        __syncthreads();
#pragma unroll 4
        for (int kk = 0; kk < 32; kk++) {
            u64t h0 = hst8[kk*32 + bg*2 + 0];
            u64t h1 = hst8[kk*32 + bg*2 + 1];
#pragma unroll
            for (int v = 0; v < 4; v++) {
                u64t wd = dup64(wst[(og*4 + v)*36 + kk]);
                fma2(acc[0][v], h0, wd);
                fma2(acc[1][v], h1, wd);
            }
        }
    }

    __syncthreads();
#pragma unroll
    for (int u = 0; u < 2; u++) {
#pragma unroll
        for (int v = 0; v < 4; v++) {
            float2 p = up2(acc[u][v]);
            int o  = og * 4 + v;
            int b0 = bg * 4 + u * 2;
            float bias = fc_b[o];
            L[(b0 + 0)*65 + o] = p.x + bias;
            L[(b0 + 1)*65 + o] = p.y + bias;
        }
    }
    __syncthreads();

    const int w = tid >> 5, lane = tid & 31;
#pragma unroll
    for (int rr = 0; rr < 8; rr++) {
        int b = w * 8 + rr;
        float v0 = L[b*65 + lane], v1 = L[b*65 + 32 + lane];
        float mx = fmaxf(v0, v1);
#pragma unroll
        for (int o = 16; o > 0; o >>= 1) mx = fmaxf(mx, __shfl_xor_sync(0xffffffffu, mx, o));
        float se = expf(v0 - mx) + expf(v1 - mx);
#pragma unroll
        for (int o = 16; o > 0; o >>= 1) se += __shfl_xor_sync(0xffffffffu, se, o);
        float lse = logf(se) + mx;
        float* op = out + ((size_t)b * SS + s) * D_OUT;
        op[lane]      = v0 - lse;
        op[lane + 32] = v1 - lse;
    }
}

// ==============================================================================
extern "C" void kernel_launch(void* const* d_in, const int* in_sizes, int n_in,
                              void* d_out, int out_size)
{
    (void)in_sizes; (void)n_in; (void)out_size;
    const int*   x    = (const int*)  d_in[0];
    const float* emb  = (const float*)d_in[1];
    const float* w_ih = (const float*)d_in[2];
    const float* w_hh = (const float*)d_in[3];
    const float* b_ih = (const float*)d_in[4];
    const float* b_hh = (const float*)d_in[5];
    const float* fc_w = (const float*)d_in[6];
    const float* fc_b = (const float*)d_in[7];
    float* out = (float*)d_out;

    const int rec_smem = SM_WORDS * 4;   // 202752 bytes
    cudaFuncSetAttribute(gru_persistent,
                         cudaFuncAttributeMaxDynamicSharedMemorySize, rec_smem);

    gi_gemm<<<dim3((SS * BB) / 128, D3H / 128), 256>>>(x, emb, w_ih, b_ih);
    gru_persistent<<<NCTA, 512, rec_smem>>>(w_hh, b_hh);
    fc_lsm<<<SS, 256>>>(fc_w, fc_b, out);
}

// round 11
// speedup vs baseline: 2.3732x; 1.2267x over previous
#include <cuda_runtime.h>
#include <cuda_fp16.h>
#include <math.h>

#define VOCAB 32000
#define D_IN  512
#define D_H   1024
#define D3H   3072
#define D_OUT 64
#define BB    64
#define SS    256
#define NCTA  128

typedef unsigned long long u64t;
typedef unsigned int u32t;

// ---------------- scratch (static device globals; zero-init at load) ----------
// gi transposed: [3H rows][S*B cols]  (row = gate*1024+j, col = s*64+b)
__device__ float g_gi[(size_t)D3H * SS * BB];
// h fp32 transposed: [s][j][b]  (exact, consumed by fc and z-path)
__device__ float g_hs[(size_t)SS * D_H * BB];
__device__ float g_h0[D_H * BB];                // all-zero h(-1), never written
// fp16 hi/lo split of h for the HMMA recurrence: [j][b]
__device__ unsigned short g_hh[D_H * BB];
__device__ unsigned short g_hl[D_H * BB];
__device__ unsigned short g_hbz[D_H * BB];      // zeros (step 0)
// fp16 hi/lo splits (u32-packed k-pairs) for the HMMA gi GEMM
__device__ u32t g_embh[(size_t)VOCAB * (D_IN / 2)];
__device__ u32t g_embl[(size_t)VOCAB * (D_IN / 2)];
__device__ u32t g_wihh[(size_t)D3H * (D_IN / 2)];
__device__ u32t g_wihl[(size_t)D3H * (D_IN / 2)];

// ---------------- grid barrier state (R3/R6/R8 proven protocol) ----------------
__device__ unsigned g_cnt = 0;
__device__ volatile unsigned g_flag = 0;        // cumulative barriers passed (monotonic)

// ---------------- helpers -------------------------------------------------------
__device__ __forceinline__ void fma2(u64t& c, u64t a, u64t b) {
    asm("fma.rn.f32x2 %0, %1, %2, %0;" : "+l"(c) : "l"(a), "l"(b));
}
__device__ __forceinline__ float2 up2(u64t v) {
    float2 r;
    asm("mov.b64 {%0, %1}, %2;" : "=f"(r.x), "=f"(r.y) : "l"(v));
    return r;
}
__device__ __forceinline__ u64t dup64(float w) {
    u64t r;
    asm("mov.b64 %0, {%1, %1};" : "=l"(r) : "f"(w));
    return r;
}
__device__ __forceinline__ u32t prmt(u32t a, u32t b, u32t s) {
    u32t d;
    asm("prmt.b32 %0, %1, %2, %3;" : "=r"(d) : "r"(a), "r"(b), "r"(s));
    return d;
}
// mma.sync m16n8k16 f16 -> f32 (sm_80 baseline PTX; compiles on base sm_103)
__device__ __forceinline__ void mma16816(float* d, u32t a0, u32t a1, u32t a2, u32t a3,
                                         u32t b0, u32t b1) {
    asm volatile(
        "mma.sync.aligned.m16n8k16.row.col.f32.f16.f16.f32 "
        "{%0,%1,%2,%3}, {%4,%5,%6,%7}, {%8,%9}, {%0,%1,%2,%3};"
        : "+f"(d[0]), "+f"(d[1]), "+f"(d[2]), "+f"(d[3])
        : "r"(a0), "r"(a1), "r"(a2), "r"(a3), "r"(b0), "r"(b1));
}

// ==============================================================================
// Kernel 0: fp32 -> packed fp16 hi/lo split (k-pair u32). Grid-stride over pairs.
// ==============================================================================
__global__ __launch_bounds__(256) void conv_split(
    const float* __restrict__ src, u32t* __restrict__ dh, u32t* __restrict__ dl,
    int n2)
{
    int i = blockIdx.x * blockDim.x + threadIdx.x;
    if (i < n2) {
        float2 v = ((const float2*)src)[i];
        __half h0 = __float2half_rn(v.x);
        __half l0 = __float2half_rn(v.x - __half2float(h0));
        __half h1 = __float2half_rn(v.y);
        __half l1 = __float2half_rn(v.y - __half2float(h1));
        dh[i] = (u32t)__half_as_ushort(h0) | ((u32t)__half_as_ushort(h1) << 16);
        dl[i] = (u32t)__half_as_ushort(l0) | ((u32t)__half_as_ushort(l1) << 16);
    }
}

// ==============================================================================
// Kernel 1: gi GEMM via HMMA hi/lo.
// g_gi[m][n] = sum_d w_ih[m][d] * emb[x(n)][d] + b_ih[m]
// M=3072 (w rows), N=16384 (tokens), K=512. Tile 128x128xK, 16 chunks of 32.
// 256 threads = 8 warps (2M x 4N), warp tile 64x32, m16n8k16, 3 products.
// SMEM row-major [row][k2] pad 20 (conflict-free fragment loads).
// ==============================================================================
#define GAH 0
#define GAL 2560
#define GBH 5120
#define GBL 7680
#define GBUF 10240      // u32 per buffer; 2 buffers = 20480 u32 = 80 KB

__global__ void __launch_bounds__(256, 1) gi_hmma(
    const int* __restrict__ x, const float* __restrict__ b_ih)
{
    extern __shared__ u32t smw[];

    const int tid  = threadIdx.x;
    const int lane = tid & 31;
    const int wid  = tid >> 5;
    const int m_blk = blockIdx.y * 128;
    const int n_blk = blockIdx.x * 128;
    const int wm = wid & 1, wn = wid >> 1;

    // staging identity: this thread owns rows r0=tid>>2 and r0+64, k2-quad q4
    const int r0 = tid >> 2, q4 = tid & 3;
    int n0 = n_blk + r0, n1 = n0 + 64;
    const size_t tok0 = (size_t)x[(n0 & 63) * SS + (n0 >> 6)] * 256;
    const size_t tok1 = (size_t)x[(n1 & 63) * SS + (n1 >> 6)] * 256;
    const size_t wr0 = (size_t)(m_blk + r0) * 256;
    const size_t wr1 = (size_t)(m_blk + r0 + 64) * 256;

    float d[4][4][4];
#pragma unroll
    for (int mt = 0; mt < 4; mt++)
#pragma unroll
        for (int nt = 0; nt < 4; nt++)
#pragma unroll
            for (int u = 0; u < 4; u++) d[mt][nt][u] = 0.f;

    // ---- stage chunk 0 ----
    {
        u32t* B = smw;
        *(uint4*)&B[GAH + r0 * 20 + q4 * 4]        = *(const uint4*)&g_wihh[wr0 + q4 * 4];
        *(uint4*)&B[GAH + (r0 + 64) * 20 + q4 * 4] = *(const uint4*)&g_wihh[wr1 + q4 * 4];
        *(uint4*)&B[GAL + r0 * 20 + q4 * 4]        = *(const uint4*)&g_wihl[wr0 + q4 * 4];
        *(uint4*)&B[GAL + (r0 + 64) * 20 + q4 * 4] = *(const uint4*)&g_wihl[wr1 + q4 * 4];
        *(uint4*)&B[GBH + r0 * 20 + q4 * 4]        = *(const uint4*)&g_embh[tok0 + q4 * 4];
        *(uint4*)&B[GBH + (r0 + 64) * 20 + q4 * 4] = *(const uint4*)&g_embh[tok1 + q4 * 4];
        *(uint4*)&B[GBL + r0 * 20 + q4 * 4]        = *(const uint4*)&g_embl[tok0 + q4 * 4];
        *(uint4*)&B[GBL + (r0 + 64) * 20 + q4 * 4] = *(const uint4*)&g_embl[tok1 + q4 * 4];
    }
    __syncthreads();

    for (int ch = 0; ch < 16; ch++) {
        // prefetch chunk ch+1 into registers
        uint4 va[4], vb[4];
        if (ch < 15) {
            int o = (ch + 1) * 16 + q4 * 4;
            va[0] = *(const uint4*)&g_wihh[wr0 + o];
            va[1] = *(const uint4*)&g_wihh[wr1 + o];
            va[2] = *(const uint4*)&g_wihl[wr0 + o];
            va[3] = *(const uint4*)&g_wihl[wr1 + o];
            vb[0] = *(const uint4*)&g_embh[tok0 + o];
            vb[1] = *(const uint4*)&g_embh[tok1 + o];
            vb[2] = *(const uint4*)&g_embl[tok0 + o];
            vb[3] = *(const uint4*)&g_embl[tok1 + o];
        }

        // compute chunk ch
        const u32t* S = smw + (ch & 1) * GBUF;
#pragma unroll
        for (int kt = 0; kt < 2; kt++) {
            const int k2b = kt * 8 + (lane & 3);
            u32t ah[4][4], al[4][4], bh[4][2], bl[4][2];
#pragma unroll
            for (int mt = 0; mt < 4; mt++) {
                int r = wm * 64 + mt * 16 + (lane >> 2);
                ah[mt][0] = S[GAH + r * 20 + k2b];
                ah[mt][1] = S[GAH + (r + 8) * 20 + k2b];
                ah[mt][2] = S[GAH + r * 20 + k2b + 4];
                ah[mt][3] = S[GAH + (r + 8) * 20 + k2b + 4];
                al[mt][0] = S[GAL + r * 20 + k2b];
                al[mt][1] = S[GAL + (r + 8) * 20 + k2b];
                al[mt][2] = S[GAL + r * 20 + k2b + 4];
                al[mt][3] = S[GAL + (r + 8) * 20 + k2b + 4];
            }
#pragma unroll
            for (int nt = 0; nt < 4; nt++) {
                int c = wn * 32 + nt * 8 + (lane >> 2);
                bh[nt][0] = S[GBH + c * 20 + k2b];
                bh[nt][1] = S[GBH + c * 20 + k2b + 4];
                bl[nt][0] = S[GBL + c * 20 + k2b];
                bl[nt][1] = S[GBL + c * 20 + k2b + 4];
            }
#pragma unroll
            for (int mt = 0; mt < 4; mt++)
#pragma unroll
                for (int nt = 0; nt < 4; nt++) {
                    mma16816(d[mt][nt], ah[mt][0], ah[mt][1], ah[mt][2], ah[mt][3],
                             bh[nt][0], bh[nt][1]);
                    mma16816(d[mt][nt], ah[mt][0], ah[mt][1], ah[mt][2], ah[mt][3],
                             bl[nt][0], bl[nt][1]);
                    mma16816(d[mt][nt], al[mt][0], al[mt][1], al[mt][2], al[mt][3],
                             bh[nt][0], bh[nt][1]);
                }
        }

        if (ch < 15) {
            u32t* B = smw + ((ch + 1) & 1) * GBUF;
            *(uint4*)&B[GAH + r0 * 20 + q4 * 4]        = va[0];
            *(uint4*)&B[GAH + (r0 + 64) * 20 + q4 * 4] = va[1];
            *(uint4*)&B[GAL + r0 * 20 + q4 * 4]        = va[2];
            *(uint4*)&B[GAL + (r0 + 64) * 20 + q4 * 4] = va[3];
            *(uint4*)&B[GBH + r0 * 20 + q4 * 4]        = vb[0];
            *(uint4*)&B[GBH + (r0 + 64) * 20 + q4 * 4] = vb[1];
            *(uint4*)&B[GBL + r0 * 20 + q4 * 4]        = vb[2];
            *(uint4*)&B[GBL + (r0 + 64) * 20 + q4 * 4] = vb[3];
            __syncthreads();
        }
    }

    // ---- epilogue: bias + store to g_gi[m][n] (row-major, N=16384) ----
#pragma unroll
    for (int mt = 0; mt < 4; mt++) {
        int rlo = m_blk + wm * 64 + mt * 16 + (lane >> 2);
        float b0 = b_ih[rlo], b1 = b_ih[rlo + 8];
#pragma unroll
        for (int nt = 0; nt < 4; nt++) {
            int c = n_blk + wn * 32 + nt * 8 + 2 * (lane & 3);
            *(float2*)&g_gi[(size_t)rlo * (SS * BB) + c] =
                make_float2(d[mt][nt][0] + b0, d[mt][nt][1] + b0);
            *(float2*)&g_gi[(size_t)(rlo + 8) * (SS * BB) + c] =
                make_float2(d[mt][nt][2] + b1, d[mt][nt][3] + b1);
        }
    }
}

// ==============================================================================
// Kernel 2: PERSISTENT GRU, HMMA recurrence.  (FROZEN from R10)
// ==============================================================================
#define WH_O   0
#define WL_O   12288
#define HB_O   24576
#define RED_O  43008
#define SM_WORDS 50688

__global__ void __launch_bounds__(512, 1) gru_persistent(
    const float* __restrict__ w_hh, const float* __restrict__ b_hh)
{
    extern __shared__ u32t smw[];
    float* redf = (float*)(smw + RED_O);

    const int tid  = threadIdx.x;
    const int j0   = blockIdx.x * 8;
    const int wid  = tid >> 5;
    const int lane = tid & 31;

    // ---- one-time: W slice -> fp16 hi/lo, layout [k2 global][24 n] ----
    {
        int k2 = tid;
#pragma unroll 1
        for (int n = 0; n < 24; n++) {
            int g = n >> 3, jj = n & 7;
            float2 wv = *(const float2*)(w_hh + (size_t)(g * D_H + j0 + jj) * D_H + k2 * 2);
            __half h0 = __float2half_rn(wv.x);
            __half l0 = __float2half_rn(wv.x - __half2float(h0));
            __half h1 = __float2half_rn(wv.y);
            __half l1 = __float2half_rn(wv.y - __half2float(h1));
            smw[WH_O + k2 * 24 + n] = (u32t)__half_as_ushort(h0) | ((u32t)__half_as_ushort(h1) << 16);
            smw[WL_O + k2 * 24 + n] = (u32t)__half_as_ushort(l0) | ((u32t)__half_as_ushort(l1) << 16);
        }
    }

    unsigned base = 0;
    if (tid == 0) base = g_flag;
    __syncthreads();

    const int mt = wid & 3;
    const int ks = wid >> 2;
    const int mrow = mt * 16 + (lane >> 2);
    const int ncol = lane >> 2;
    const int ejj = tid >> 6, eb = tid & 63;
    const int ej  = j0 + ejj;
    const float bhr = b_hh[ej], bhz = b_hh[D_H + ej], bhn = b_hh[2 * D_H + ej];

    for (int s = 0; s < SS; s++) {
        const float* hp32 = (s == 0) ? g_h0 : (g_hs + (size_t)(s - 1) * D_H * BB);
        const unsigned short* hbh = (s == 0) ? g_hbz : g_hh;
        const unsigned short* hbl = (s == 0) ? g_hbz : g_hl;

        const float* gip = g_gi + (size_t)s * 64 + (size_t)ej * (SS * BB) + eb;
        float e_gir = gip[0];
        float e_giz = gip[(size_t)D_H * SS * BB];
        float e_gin = gip[(size_t)2 * D_H * SS * BB];
        float e_hp  = hp32[(size_t)ej * 64 + eb];

        float d[3][4];
#pragma unroll
        for (int nt = 0; nt < 3; nt++)
#pragma unroll
            for (int u = 0; u < 4; u++) d[nt][u] = 0.f;

#pragma unroll
        for (int uu = 0; uu < 2; uu++) {
            int u = tid + uu * 512;
            int half = u >> 9, r = u & 511, k2 = r >> 3, bo = r & 7;
            const unsigned short* src = (half ? hbl : hbh) + (size_t)(2 * k2) * 64 + bo * 8;
            uint4 r0 = *(const uint4*)src;
            uint4 r1 = *(const uint4*)(src + 64);
            u32t* dst = smw + HB_O + half * 4608 + k2 * 72 + bo * 8;
            dst[0] = prmt(r0.x, r1.x, 0x5410); dst[1] = prmt(r0.x, r1.x, 0x7632);
            dst[2] = prmt(r0.y, r1.y, 0x5410); dst[3] = prmt(r0.y, r1.y, 0x7632);
            dst[4] = prmt(r0.z, r1.z, 0x5410); dst[5] = prmt(r0.z, r1.z, 0x7632);
            dst[6] = prmt(r0.w, r1.w, 0x5410); dst[7] = prmt(r0.w, r1.w, 0x7632);
        }
        __syncthreads();

        for (int g = 0; g < 8; g++) {
            uint4 pr[2][2];
            if (g < 7) {
#pragma unroll
                for (int uu = 0; uu < 2; uu++) {
                    int u = tid + uu * 512;
                    int half = u >> 9, r = u & 511, k2 = r >> 3, bo = r & 7;
                    const unsigned short* src = (half ? hbl : hbh)
                        + (size_t)((g + 1) * 128 + 2 * k2) * 64 + bo * 8;
                    pr[uu][0] = *(const uint4*)src;
                    pr[uu][1] = *(const uint4*)(src + 64);
                }
            }

            const u32t* hb = smw + HB_O + (g & 1) * 9216;
#pragma unroll
            for (int it = 0; it < 2; it++) {
                int tl = ks + it * 4;
                int ka = tl * 8 + (lane & 3);
                u32t ah0 = hb[ka * 72 + mrow];
                u32t ah1 = hb[ka * 72 + mrow + 8];
                u32t ah2 = hb[(ka + 4) * 72 + mrow];
                u32t ah3 = hb[(ka + 4) * 72 + mrow + 8];
                u32t al0 = hb[4608 + ka * 72 + mrow];
                u32t al1 = hb[4608 + ka * 72 + mrow + 8];
                u32t al2 = hb[4608 + (ka + 4) * 72 + mrow];
                u32t al3 = hb[4608 + (ka + 4) * 72 + mrow + 8];
                int kw = (g * 64 + ka) * 24 + ncol;
#pragma unroll
                for (int nt = 0; nt < 3; nt++) {
                    u32t bh0 = smw[WH_O + kw + nt * 8];
                    u32t bh1 = smw[WH_O + kw + 96 + nt * 8];
                    u32t bl0 = smw[WL_O + kw + nt * 8];
                    u32t bl1 = smw[WL_O + kw + 96 + nt * 8];
                    mma16816(d[nt], ah0, ah1, ah2, ah3, bh0, bh1);
                    mma16816(d[nt], ah0, ah1, ah2, ah3, bl0, bl1);
                    mma16816(d[nt], al0, al1, al2, al3, bh0, bh1);
                }
            }

            if (g < 7) {
                u32t* bufbase = smw + HB_O + ((g + 1) & 1) * 9216;
#pragma unroll
                for (int uu = 0; uu < 2; uu++) {
                    int u = tid + uu * 512;
                    int half = u >> 9, r = u & 511, k2 = r >> 3, bo = r & 7;
                    u32t* dst = bufbase + half * 4608 + k2 * 72 + bo * 8;
                    uint4 r0 = pr[uu][0], r1 = pr[uu][1];
                    dst[0] = prmt(r0.x, r1.x, 0x5410); dst[1] = prmt(r0.x, r1.x, 0x7632);
                    dst[2] = prmt(r0.y, r1.y, 0x5410); dst[3] = prmt(r0.y, r1.y, 0x7632);
                    dst[4] = prmt(r0.z, r1.z, 0x5410); dst[5] = prmt(r0.z, r1.z, 0x7632);
                    dst[6] = prmt(r0.w, r1.w, 0x5410); dst[7] = prmt(r0.w, r1.w, 0x7632);
                }
                __syncthreads();
            }
        }

#pragma unroll
        for (int nt = 0; nt < 3; nt++) {
            int rb = (ks * 64 + mt * 16 + (lane >> 2)) * 30 + nt * 8 + 2 * (lane & 3);
            *(float2*)&redf[rb]       = make_float2(d[nt][0], d[nt][1]);
            *(float2*)&redf[rb + 240] = make_float2(d[nt][2], d[nt][3]);
        }
        __syncthreads();

        {
            float ghr = 0.f, ghz = 0.f, ghn = 0.f;
#pragma unroll
            for (int k = 0; k < 4; k++) {
                int rb = (k * 64 + eb) * 30;
                ghr += redf[rb + ejj];
                ghz += redf[rb + 8 + ejj];
                ghn += redf[rb + 16 + ejj];
            }
            float r = 1.f / (1.f + expf(-(e_gir + ghr + bhr)));
            float z = 1.f / (1.f + expf(-(e_giz + ghz + bhz)));
            float n = tanhf(e_gin + r * (ghn + bhn));
            float h = (1.f - z) * n + z * e_hp;
            g_hs[(size_t)s * D_H * BB + (size_t)ej * 64 + eb] = h;
            __half hh = __float2half_rn(h);
            __half hl = __float2half_rn(h - __half2float(hh));
            g_hh[ej * 64 + eb] = __half_as_ushort(hh);
            g_hl[ej * 64 + eb] = __half_as_ushort(hl);
        }

        __syncthreads();
        if (tid == 0) {
            __threadfence();
            unsigned target = base + (unsigned)(s + 1);
            unsigned old = atomicAdd(&g_cnt, 1u);
            if (old == NCTA - 1) {
                atomicExch(&g_cnt, 0u);
                __threadfence();
                atomicExch((unsigned*)&g_flag, target);
            } else {
                while (g_flag < target) { }
            }
            __threadfence();
        }
        __syncthreads();
    }
}

// ==============================================================================
// Kernel 3: fc + log_softmax (unchanged)
// ==============================================================================
__global__ __launch_bounds__(256) void fc_lsm(
    const float* __restrict__ fc_w, const float* __restrict__ fc_b,
    float* __restrict__ out)
{
    __shared__ float hst[32 * 64];
    __shared__ float wst[64 * 36];
    __shared__ float L  [64 * 65];

    const int tid = threadIdx.x;
    const int s   = blockIdx.x;
    const float* hs_s = g_hs + (size_t)s * D_H * BB;
    const int og = tid & 15, bg = tid >> 4;

    u64t acc[2][4];
#pragma unroll
    for (int u = 0; u < 2; u++)
#pragma unroll
        for (int v = 0; v < 4; v++) acc[u][v] = 0ull;
    u64t* hst8 = (u64t*)hst;

    for (int k0 = 0; k0 < D_H; k0 += 32) {
        __syncthreads();
#pragma unroll
        for (int i = 0; i < 2; i++) {
            int q = tid + i * 256;
            int kl = q >> 4, bq = q & 15;
            *(float4*)(hst + kl*64 + bq*4) =
                *(const float4*)(hs_s + (size_t)(k0 + kl) * 64 + bq * 4);
        }
#pragma unroll
        for (int i = 0; i < 2; i++) {
            int q = tid + i * 256;
            int o = q >> 3, kq = q & 7;
            *(float4*)(wst + o*36 + kq*4) =
                *(const float4*)(fc_w + (size_t)o * D_H + k0 + kq * 4);
        }
        __syncthreads();
#pragma unroll 4
        for (int kk = 0; kk < 32; kk++) {
            u64t h0 = hst8[kk*32 + bg*2 + 0];
            u64t h1 = hst8[kk*32 + bg*2 + 1];
#pragma unroll
            for (int v = 0; v < 4; v++) {
                u64t wd = dup64(wst[(og*4 + v)*36 + kk]);
                fma2(acc[0][v], h0, wd);
                fma2(acc[1][v], h1, wd);
            }
        }
    }

    __syncthreads();
#pragma unroll
    for (int u = 0; u < 2; u++) {
#pragma unroll
        for (int v = 0; v < 4; v++) {
            float2 p = up2(acc[u][v]);
            int o  = og * 4 + v;
            int b0 = bg * 4 + u * 2;
            float bias = fc_b[o];
            L[(b0 + 0)*65 + o] = p.x + bias;
            L[(b0 + 1)*65 + o] = p.y + bias;
        }
    }
    __syncthreads();

    const int w = tid >> 5, lane = tid & 31;
#pragma unroll
    for (int rr = 0; rr < 8; rr++) {
        int b = w * 8 + rr;
        float v0 = L[b*65 + lane], v1 = L[b*65 + 32 + lane];
        float mx = fmaxf(v0, v1);
#pragma unroll
        for (int o = 16; o > 0; o >>= 1) mx = fmaxf(mx, __shfl_xor_sync(0xffffffffu, mx, o));
        float se = expf(v0 - mx) + expf(v1 - mx);
#pragma unroll
        for (int o = 16; o > 0; o >>= 1) se += __shfl_xor_sync(0xffffffffu, se, o);
        float lse = logf(se) + mx;
        float* op = out + ((size_t)b * SS + s) * D_OUT;
        op[lane]      = v0 - lse;
        op[lane + 32] = v1 - lse;
    }
}

// ==============================================================================
extern "C" void kernel_launch(void* const* d_in, const int* in_sizes, int n_in,
                              void* d_out, int out_size)
{
    (void)in_sizes; (void)n_in; (void)out_size;
    const int*   x    = (const int*)  d_in[0];
    const float* emb  = (const float*)d_in[1];
    const float* w_ih = (const float*)d_in[2];
    const float* w_hh = (const float*)d_in[3];
    const float* b_ih = (const float*)d_in[4];
    const float* b_hh = (const float*)d_in[5];
    const float* fc_w = (const float*)d_in[6];
    const float* fc_b = (const float*)d_in[7];
    float* out = (float*)d_out;

    const int rec_smem = SM_WORDS * 4;   // 202752 B
    cudaFuncSetAttribute(gru_persistent,
                         cudaFuncAttributeMaxDynamicSharedMemorySize, rec_smem);
    const int gi_smem = 2 * GBUF * 4;    // 81920 B
    cudaFuncSetAttribute(gi_hmma,
                         cudaFuncAttributeMaxDynamicSharedMemorySize, gi_smem);

    u32t *embh, *embl, *wihh, *wihl;
    cudaGetSymbolAddress((void**)&embh, g_embh);
    cudaGetSymbolAddress((void**)&embl, g_embl);
    cudaGetSymbolAddress((void**)&wihh, g_wihh);
    cudaGetSymbolAddress((void**)&wihl, g_wihl);

    conv_split<<<(VOCAB * 256 + 255) / 256, 256>>>(emb, embh, embl, VOCAB * 256);
    conv_split<<<(D3H * 256 + 255) / 256, 256>>>(w_ih, wihh, wihl, D3H * 256);
    gi_hmma<<<dim3((SS * BB) / 128, D3H / 128), 256, gi_smem>>>(x, b_ih);
    gru_persistent<<<NCTA, 512, rec_smem>>>(w_hh, b_hh);
    fc_lsm<<<SS, 256>>>(fc_w, fc_b, out);
}

// round 12
// speedup vs baseline: 2.4055x; 1.0136x over previous
#include <cuda_runtime.h>
#include <cuda_fp16.h>
#include <math.h>

#define VOCAB 32000
#define D_IN  512
#define D_H   1024
#define D3H   3072
#define D_OUT 64
#define BB    64
#define SS    256
#define NCTA  128

typedef unsigned long long u64t;
typedef unsigned int u32t;

// ---------------- scratch (static device globals; zero-init at load) ----------
// gi transposed: [3H rows][S*B cols]  (row = gate*1024+j, col = s*64+b)
__device__ float g_gi[(size_t)D3H * SS * BB];
// h fp32 transposed: [s][j][b]  (exact, consumed by fc and z-path)
__device__ float g_hs[(size_t)SS * D_H * BB];
__device__ float g_h0[D_H * BB];                // all-zero h(-1), never written
// fp16 hi/lo split of h for the HMMA recurrence: [j][b]
__device__ unsigned short g_hh[D_H * BB];
__device__ unsigned short g_hl[D_H * BB];
__device__ unsigned short g_hbz[D_H * BB];      // zeros (step 0)
// fp16 hi/lo splits (u32-packed k-pairs) for the HMMA gi GEMM
__device__ u32t g_embh[(size_t)VOCAB * (D_IN / 2)];
__device__ u32t g_embl[(size_t)VOCAB * (D_IN / 2)];
__device__ u32t g_wihh[(size_t)D3H * (D_IN / 2)];
__device__ u32t g_wihl[(size_t)D3H * (D_IN / 2)];

// ---------------- grid barrier state (R3/R6/R8 proven protocol) ----------------
__device__ unsigned g_cnt = 0;
__device__ volatile unsigned g_flag = 0;        // cumulative barriers passed (monotonic)

// ---------------- helpers -------------------------------------------------------
__device__ __forceinline__ void fma2(u64t& c, u64t a, u64t b) {
    asm("fma.rn.f32x2 %0, %1, %2, %0;" : "+l"(c) : "l"(a), "l"(b));
}
__device__ __forceinline__ float2 up2(u64t v) {
    float2 r;
    asm("mov.b64 {%0, %1}, %2;" : "=f"(r.x), "=f"(r.y) : "l"(v));
    return r;
}
__device__ __forceinline__ u64t dup64(float w) {
    u64t r;
    asm("mov.b64 %0, {%1, %1};" : "=l"(r) : "f"(w));
    return r;
}
__device__ __forceinline__ u32t prmt(u32t a, u32t b, u32t s) {
    u32t d;
    asm("prmt.b32 %0, %1, %2, %3;" : "=r"(d) : "r"(a), "r"(b), "r"(s));
    return d;
}
// mma.sync m16n8k16 f16 -> f32 (sm_80 baseline PTX; compiles on base sm_103)
__device__ __forceinline__ void mma16816(float* d, u32t a0, u32t a1, u32t a2, u32t a3,
                                         u32t b0, u32t b1) {
    asm volatile(
        "mma.sync.aligned.m16n8k16.row.col.f32.f16.f16.f32 "
        "{%0,%1,%2,%3}, {%4,%5,%6,%7}, {%8,%9}, {%0,%1,%2,%3};"
        : "+f"(d[0]), "+f"(d[1]), "+f"(d[2]), "+f"(d[3])
        : "r"(a0), "r"(a1), "r"(a2), "r"(a3), "r"(b0), "r"(b1));
}

// ==============================================================================
// Kernel 0: fp32 -> packed fp16 hi/lo split (k-pair u32). Grid-stride over pairs.
// ==============================================================================
__global__ __launch_bounds__(256) void conv_split(
    const float* __restrict__ src, u32t* __restrict__ dh, u32t* __restrict__ dl,
    int n2)
{
    int i = blockIdx.x * blockDim.x + threadIdx.x;
    if (i < n2) {
        float2 v = ((const float2*)src)[i];
        __half h0 = __float2half_rn(v.x);
        __half l0 = __float2half_rn(v.x - __half2float(h0));
        __half h1 = __float2half_rn(v.y);
        __half l1 = __float2half_rn(v.y - __half2float(h1));
        dh[i] = (u32t)__half_as_ushort(h0) | ((u32t)__half_as_ushort(h1) << 16);
        dl[i] = (u32t)__half_as_ushort(l0) | ((u32t)__half_as_ushort(l1) << 16);
    }
}

// ==============================================================================
// Kernel 1: gi GEMM via HMMA hi/lo.   (FROZEN from R11)
// ==============================================================================
#define GAH 0
#define GAL 2560
#define GBH 5120
#define GBL 7680
#define GBUF 10240      // u32 per buffer; 2 buffers = 20480 u32 = 80 KB

__global__ void __launch_bounds__(256, 1) gi_hmma(
    const int* __restrict__ x, const float* __restrict__ b_ih)
{
    extern __shared__ u32t smw[];

    const int tid  = threadIdx.x;
    const int lane = tid & 31;
    const int wid  = tid >> 5;
    const int m_blk = blockIdx.y * 128;
    const int n_blk = blockIdx.x * 128;
    const int wm = wid & 1, wn = wid >> 1;

    const int r0 = tid >> 2, q4 = tid & 3;
    int n0 = n_blk + r0, n1 = n0 + 64;
    const size_t tok0 = (size_t)x[(n0 & 63) * SS + (n0 >> 6)] * 256;
    const size_t tok1 = (size_t)x[(n1 & 63) * SS + (n1 >> 6)] * 256;
    const size_t wr0 = (size_t)(m_blk + r0) * 256;
    const size_t wr1 = (size_t)(m_blk + r0 + 64) * 256;

    float d[4][4][4];
#pragma unroll
    for (int mt = 0; mt < 4; mt++)
#pragma unroll
        for (int nt = 0; nt < 4; nt++)
#pragma unroll
            for (int u = 0; u < 4; u++) d[mt][nt][u] = 0.f;

    {
        u32t* B = smw;
        *(uint4*)&B[GAH + r0 * 20 + q4 * 4]        = *(const uint4*)&g_wihh[wr0 + q4 * 4];
        *(uint4*)&B[GAH + (r0 + 64) * 20 + q4 * 4] = *(const uint4*)&g_wihh[wr1 + q4 * 4];
        *(uint4*)&B[GAL + r0 * 20 + q4 * 4]        = *(const uint4*)&g_wihl[wr0 + q4 * 4];
        *(uint4*)&B[GAL + (r0 + 64) * 20 + q4 * 4] = *(const uint4*)&g_wihl[wr1 + q4 * 4];
        *(uint4*)&B[GBH + r0 * 20 + q4 * 4]        = *(const uint4*)&g_embh[tok0 + q4 * 4];
        *(uint4*)&B[GBH + (r0 + 64) * 20 + q4 * 4] = *(const uint4*)&g_embh[tok1 + q4 * 4];
        *(uint4*)&B[GBL + r0 * 20 + q4 * 4]        = *(const uint4*)&g_embl[tok0 + q4 * 4];
        *(uint4*)&B[GBL + (r0 + 64) * 20 + q4 * 4] = *(const uint4*)&g_embl[tok1 + q4 * 4];
    }
    __syncthreads();

    for (int ch = 0; ch < 16; ch++) {
        uint4 va[4], vb[4];
        if (ch < 15) {
            int o = (ch + 1) * 16 + q4 * 4;
            va[0] = *(const uint4*)&g_wihh[wr0 + o];
            va[1] = *(const uint4*)&g_wihh[wr1 + o];
            va[2] = *(const uint4*)&g_wihl[wr0 + o];
            va[3] = *(const uint4*)&g_wihl[wr1 + o];
            vb[0] = *(const uint4*)&g_embh[tok0 + o];
            vb[1] = *(const uint4*)&g_embh[tok1 + o];
            vb[2] = *(const uint4*)&g_embl[tok0 + o];
            vb[3] = *(const uint4*)&g_embl[tok1 + o];
        }

        const u32t* S = smw + (ch & 1) * GBUF;
#pragma unroll
        for (int kt = 0; kt < 2; kt++) {
            const int k2b = kt * 8 + (lane & 3);
            u32t ah[4][4], al[4][4], bh[4][2], bl[4][2];
#pragma unroll
            for (int mt = 0; mt < 4; mt++) {
                int r = wm * 64 + mt * 16 + (lane >> 2);
                ah[mt][0] = S[GAH + r * 20 + k2b];
                ah[mt][1] = S[GAH + (r + 8) * 20 + k2b];
                ah[mt][2] = S[GAH + r * 20 + k2b + 4];
                ah[mt][3] = S[GAH + (r + 8) * 20 + k2b + 4];
                al[mt][0] = S[GAL + r * 20 + k2b];
                al[mt][1] = S[GAL + (r + 8) * 20 + k2b];
                al[mt][2] = S[GAL + r * 20 + k2b + 4];
                al[mt][3] = S[GAL + (r + 8) * 20 + k2b + 4];
            }
#pragma unroll
            for (int nt = 0; nt < 4; nt++) {
                int c = wn * 32 + nt * 8 + (lane >> 2);
                bh[nt][0] = S[GBH + c * 20 + k2b];
                bh[nt][1] = S[GBH + c * 20 + k2b + 4];
                bl[nt][0] = S[GBL + c * 20 + k2b];
                bl[nt][1] = S[GBL + c * 20 + k2b + 4];
            }
#pragma unroll
            for (int mt = 0; mt < 4; mt++)
#pragma unroll
                for (int nt = 0; nt < 4; nt++) {
                    mma16816(d[mt][nt], ah[mt][0], ah[mt][1], ah[mt][2], ah[mt][3],
                             bh[nt][0], bh[nt][1]);
                    mma16816(d[mt][nt], ah[mt][0], ah[mt][1], ah[mt][2], ah[mt][3],
                             bl[nt][0], bl[nt][1]);
                    mma16816(d[mt][nt], al[mt][0], al[mt][1], al[mt][2], al[mt][3],
                             bh[nt][0], bh[nt][1]);
                }
        }

        if (ch < 15) {
            u32t* B = smw + ((ch + 1) & 1) * GBUF;
            *(uint4*)&B[GAH + r0 * 20 + q4 * 4]        = va[0];
            *(uint4*)&B[GAH + (r0 + 64) * 20 + q4 * 4] = va[1];
            *(uint4*)&B[GAL + r0 * 20 + q4 * 4]        = va[2];
            *(uint4*)&B[GAL + (r0 + 64) * 20 + q4 * 4] = va[3];
            *(uint4*)&B[GBH + r0 * 20 + q4 * 4]        = vb[0];
            *(uint4*)&B[GBH + (r0 + 64) * 20 + q4 * 4] = vb[1];
            *(uint4*)&B[GBL + r0 * 20 + q4 * 4]        = vb[2];
            *(uint4*)&B[GBL + (r0 + 64) * 20 + q4 * 4] = vb[3];
            __syncthreads();
        }
    }

#pragma unroll
    for (int mt = 0; mt < 4; mt++) {
        int rlo = m_blk + wm * 64 + mt * 16 + (lane >> 2);
        float b0 = b_ih[rlo], b1 = b_ih[rlo + 8];
#pragma unroll
        for (int nt = 0; nt < 4; nt++) {
            int c = n_blk + wn * 32 + nt * 8 + 2 * (lane & 3);
            *(float2*)&g_gi[(size_t)rlo * (SS * BB) + c] =
                make_float2(d[mt][nt][0] + b0, d[mt][nt][1] + b0);
            *(float2*)&g_gi[(size_t)(rlo + 8) * (SS * BB) + c] =
                make_float2(d[mt][nt][2] + b1, d[mt][nt][3] + b1);
        }
    }
}

// ==============================================================================
// Kernel 2: PERSISTENT GRU, HMMA recurrence — distance-2 prefetch, 3 buffers.
// ==============================================================================
#define WH_O   0
#define WL_O   12288
#define HB_O   24576          // 3 buffers x 9216 u32
#define RED_O  43008          // aliases buf2 (last buf2 reader = chunk 5; safe)
#define SM_WORDS 52224        // 208896 bytes

__device__ __forceinline__ void rec_ldg(const unsigned short* hbh,
                                        const unsigned short* hbl,
                                        int g, int tid, uint4 pr[2][2])
{
#pragma unroll
    for (int uu = 0; uu < 2; uu++) {
        int u = tid + uu * 512;
        int half = u >> 9, r = u & 511, k2 = r >> 3, bo = r & 7;
        const unsigned short* src = (half ? hbl : hbh)
            + (size_t)(g * 128 + 2 * k2) * 64 + bo * 8;
        pr[uu][0] = *(const uint4*)src;
        pr[uu][1] = *(const uint4*)(src + 64);
    }
}
__device__ __forceinline__ void rec_sts(u32t* smw, int bufsel, int tid,
                                        const uint4 pr[2][2])
{
    u32t* bufbase = smw + HB_O + bufsel * 9216;
#pragma unroll
    for (int uu = 0; uu < 2; uu++) {
        int u = tid + uu * 512;
        int half = u >> 9, r = u & 511, k2 = r >> 3, bo = r & 7;
        u32t* dst = bufbase + half * 4608 + k2 * 72 + bo * 8;
        uint4 r0 = pr[uu][0], r1 = pr[uu][1];
        dst[0] = prmt(r0.x, r1.x, 0x5410); dst[1] = prmt(r0.x, r1.x, 0x7632);
        dst[2] = prmt(r0.y, r1.y, 0x5410); dst[3] = prmt(r0.y, r1.y, 0x7632);
        dst[4] = prmt(r0.z, r1.z, 0x5410); dst[5] = prmt(r0.z, r1.z, 0x7632);
        dst[6] = prmt(r0.w, r1.w, 0x5410); dst[7] = prmt(r0.w, r1.w, 0x7632);
    }
}

__global__ void __launch_bounds__(512, 1) gru_persistent(
    const float* __restrict__ w_hh, const float* __restrict__ b_hh)
{
    extern __shared__ u32t smw[];
    float* redf = (float*)(smw + RED_O);

    const int tid  = threadIdx.x;
    const int j0   = blockIdx.x * 8;
    const int wid  = tid >> 5;
    const int lane = tid & 31;

    // ---- one-time: W slice -> fp16 hi/lo, layout [k2 global][24 n] ----
    {
        int k2 = tid;
#pragma unroll 1
        for (int n = 0; n < 24; n++) {
            int g = n >> 3, jj = n & 7;
            float2 wv = *(const float2*)(w_hh + (size_t)(g * D_H + j0 + jj) * D_H + k2 * 2);
            __half h0 = __float2half_rn(wv.x);
            __half l0 = __float2half_rn(wv.x - __half2float(h0));
            __half h1 = __float2half_rn(wv.y);
            __half l1 = __float2half_rn(wv.y - __half2float(h1));
            smw[WH_O + k2 * 24 + n] = (u32t)__half_as_ushort(h0) | ((u32t)__half_as_ushort(h1) << 16);
            smw[WL_O + k2 * 24 + n] = (u32t)__half_as_ushort(l0) | ((u32t)__half_as_ushort(l1) << 16);
        }
    }

    unsigned base = 0;
    if (tid == 0) base = g_flag;
    __syncthreads();

    const int mt = wid & 3;
    const int ks = wid >> 2;
    const int mrow = mt * 16 + (lane >> 2);
    const int ncol = lane >> 2;
    const int ejj = tid >> 6, eb = tid & 63;
    const int ej  = j0 + ejj;
    const float bhr = b_hh[ej], bhz = b_hh[D_H + ej], bhn = b_hh[2 * D_H + ej];

    for (int s = 0; s < SS; s++) {
        const float* hp32 = (s == 0) ? g_h0 : (g_hs + (size_t)(s - 1) * D_H * BB);
        const unsigned short* hbh = (s == 0) ? g_hbz : g_hh;
        const unsigned short* hbl = (s == 0) ? g_hbz : g_hl;

        // ---- issue chunk 0 & 1 loads first (post-barrier critical path) ----
        uint4 P0[2][2], P1[2][2];
        rec_ldg(hbh, hbl, 0, tid, P0);
        rec_ldg(hbh, hbl, 1, tid, P1);

        // ---- epilogue operand prefetch (overlaps with chunk loads) ----
        const float* gip = g_gi + (size_t)s * 64 + (size_t)ej * (SS * BB) + eb;
        float e_gir = gip[0];
        float e_giz = gip[(size_t)D_H * SS * BB];
        float e_gin = gip[(size_t)2 * D_H * SS * BB];
        float e_hp  = hp32[(size_t)ej * 64 + eb];

        float d[3][4];
#pragma unroll
        for (int nt = 0; nt < 3; nt++)
#pragma unroll
            for (int u = 0; u < 4; u++) d[nt][u] = 0.f;

        rec_sts(smw, 0, tid, P0);           // c0 -> buf0 (P0 now free)
        __syncthreads();

#pragma unroll
        for (int g = 0; g < 8; g++) {
            // distance-2 prefetch: c(g+2) -> P[g&1]
            if (g < 6) rec_ldg(hbh, hbl, g + 2, tid, (g & 1) ? P1 : P0);

            // compute chunk g from buf[g%3]
            const u32t* hb = smw + HB_O + (g % 3) * 9216;
#pragma unroll
            for (int it = 0; it < 2; it++) {
                int tl = ks + it * 4;
                int ka = tl * 8 + (lane & 3);
                u32t ah0 = hb[ka * 72 + mrow];
                u32t ah1 = hb[ka * 72 + mrow + 8];
                u32t ah2 = hb[(ka + 4) * 72 + mrow];
                u32t ah3 = hb[(ka + 4) * 72 + mrow + 8];
                u32t al0 = hb[4608 + ka * 72 + mrow];
                u32t al1 = hb[4608 + ka * 72 + mrow + 8];
                u32t al2 = hb[4608 + (ka + 4) * 72 + mrow];
                u32t al3 = hb[4608 + (ka + 4) * 72 + mrow + 8];
                int kw = (g * 64 + ka) * 24 + ncol;
#pragma unroll
                for (int nt = 0; nt < 3; nt++) {
                    u32t bh0 = smw[WH_O + kw + nt * 8];
                    u32t bh1 = smw[WH_O + kw + 96 + nt * 8];
                    u32t bl0 = smw[WL_O + kw + nt * 8];
                    u32t bl1 = smw[WL_O + kw + 96 + nt * 8];
                    mma16816(d[nt], ah0, ah1, ah2, ah3, bh0, bh1);
                    mma16816(d[nt], ah0, ah1, ah2, ah3, bl0, bl1);
                    mma16816(d[nt], al0, al1, al2, al3, bh0, bh1);
                }
            }

            // store c(g+1) (loaded at top of g-1, or prologue for g=0)
            if (g < 7) {
                rec_sts(smw, (g + 1) % 3, tid, ((g + 1) & 1) ? P1 : P0);
                __syncthreads();
            }
        }

        // ---- D fragments -> red (aliases buf2; chunk 5 drained at g=6 sync) ----
#pragma unroll
        for (int nt = 0; nt < 3; nt++) {
            int rb = (ks * 64 + mt * 16 + (lane >> 2)) * 30 + nt * 8 + 2 * (lane & 3);
            *(float2*)&redf[rb]       = make_float2(d[nt][0], d[nt][1]);
            *(float2*)&redf[rb + 240] = make_float2(d[nt][2], d[nt][3]);
        }
        __syncthreads();

        // ---- gate epilogue: 512 outputs, 1 per thread ----
        {
            float ghr = 0.f, ghz = 0.f, ghn = 0.f;
#pragma unroll
            for (int k = 0; k < 4; k++) {
                int rb = (k * 64 + eb) * 30;
                ghr += redf[rb + ejj];
                ghz += redf[rb + 8 + ejj];
                ghn += redf[rb + 16 + ejj];
            }
            float r = 1.f / (1.f + expf(-(e_gir + ghr + bhr)));
            float z = 1.f / (1.f + expf(-(e_giz + ghz + bhz)));
            float n = tanhf(e_gin + r * (ghn + bhn));
            float h = (1.f - z) * n + z * e_hp;
            g_hs[(size_t)s * D_H * BB + (size_t)ej * 64 + eb] = h;
            __half hh = __float2half_rn(h);
            __half hl = __float2half_rn(h - __half2float(hh));
            g_hh[ej * 64 + eb] = __half_as_ushort(hh);
            g_hl[ej * 64 + eb] = __half_as_ushort(hl);
        }

        // ---- grid barrier (proven) ----
        __syncthreads();
        if (tid == 0) {
            __threadfence();
            unsigned target = base + (unsigned)(s + 1);
            unsigned old = atomicAdd(&g_cnt, 1u);
            if (old == NCTA - 1) {
                atomicExch(&g_cnt, 0u);
                __threadfence();
                atomicExch((unsigned*)&g_flag, target);
            } else {
                while (g_flag < target) { }
            }
            __threadfence();
        }
        __syncthreads();
    }
}

// ==============================================================================
// Kernel 3: fc + log_softmax (unchanged)
// ==============================================================================
__global__ __launch_bounds__(256) void fc_lsm(
    const float* __restrict__ fc_w, const float* __restrict__ fc_b,
    float* __restrict__ out)
{
    __shared__ float hst[32 * 64];
    __shared__ float wst[64 * 36];
    __shared__ float L  [64 * 65];

    const int tid = threadIdx.x;
    const int s   = blockIdx.x;
    const float* hs_s = g_hs + (size_t)s * D_H * BB;
    const int og = tid & 15, bg = tid >> 4;

    u64t acc[2][4];
#pragma unroll
    for (int u = 0; u < 2; u++)
#pragma unroll
        for (int v = 0; v < 4; v++) acc[u][v] = 0ull;
    u64t* hst8 = (u64t*)hst;

    for (int k0 = 0; k0 < D_H; k0 += 32) {
        __syncthreads();
#pragma unroll
        for (int i = 0; i < 2; i++) {
            int q = tid + i * 256;
            int kl = q >> 4, bq = q & 15;
            *(float4*)(hst + kl*64 + bq*4) =
                *(const float4*)(hs_s + (size_t)(k0 + kl) * 64 + bq * 4);
        }
#pragma unroll
        for (int i = 0; i < 2; i++) {
            int q = tid + i * 256;
            int o = q >> 3, kq = q & 7;
            *(float4*)(wst + o*36 + kq*4) =
                *(const float4*)(fc_w + (size_t)o * D_H + k0 + kq * 4);
        }
        __syncthreads();
#pragma unroll 4
        for (int kk = 0; kk < 32; kk++) {
            u64t h0 = hst8[kk*32 + bg*2 + 0];
            u64t h1 = hst8[kk*32 + bg*2 + 1];
#pragma unroll
            for (int v = 0; v < 4; v++) {
                u64t wd = dup64(wst[(og*4 + v)*36 + kk]);
                fma2(acc[0][v], h0, wd);
                fma2(acc[1][v], h1, wd);
            }
        }
    }

    __syncthreads();
#pragma unroll
    for (int u = 0; u < 2; u++) {
#pragma unroll
        for (int v = 0; v < 4; v++) {
            float2 p = up2(acc[u][v]);
            int o  = og * 4 + v;
            int b0 = bg * 4 + u * 2;
            float bias = fc_b[o];
            L[(b0 + 0)*65 + o] = p.x + bias;
            L[(b0 + 1)*65 + o] = p.y + bias;
        }
    }
    __syncthreads();

    const int w = tid >> 5, lane = tid & 31;
#pragma unroll
    for (int rr = 0; rr < 8; rr++) {
        int b = w * 8 + rr;
        float v0 = L[b*65 + lane], v1 = L[b*65 + 32 + lane];
        float mx = fmaxf(v0, v1);
#pragma unroll
        for (int o = 16; o > 0; o >>= 1) mx = fmaxf(mx, __shfl_xor_sync(0xffffffffu, mx, o));
        float se = expf(v0 - mx) + expf(v1 - mx);
#pragma unroll
        for (int o = 16; o > 0; o >>= 1) se += __shfl_xor_sync(0xffffffffu, se, o);
        float lse = logf(se) + mx;
        float* op = out + ((size_t)b * SS + s) * D_OUT;
        op[lane]      = v0 - lse;
        op[lane + 32] = v1 - lse;
    }
}

// ==============================================================================
extern "C" void kernel_launch(void* const* d_in, const int* in_sizes, int n_in,
                              void* d_out, int out_size)
{
    (void)in_sizes; (void)n_in; (void)out_size;
    const int*   x    = (const int*)  d_in[0];
    const float* emb  = (const float*)d_in[1];
    const float* w_ih = (const float*)d_in[2];
    const float* w_hh = (const float*)d_in[3];
    const float* b_ih = (const float*)d_in[4];
    const float* b_hh = (const float*)d_in[5];
    const float* fc_w = (const float*)d_in[6];
    const float* fc_b = (const float*)d_in[7];
    float* out = (float*)d_out;

    const int rec_smem = SM_WORDS * 4;   // 208896 B
    cudaFuncSetAttribute(gru_persistent,
                         cudaFuncAttributeMaxDynamicSharedMemorySize, rec_smem);
    const int gi_smem = 2 * GBUF * 4;    // 81920 B
    cudaFuncSetAttribute(gi_hmma,
                         cudaFuncAttributeMaxDynamicSharedMemorySize, gi_smem);

    u32t *embh, *embl, *wihh, *wihl;
    cudaGetSymbolAddress((void**)&embh, g_embh);
    cudaGetSymbolAddress((void**)&embl, g_embl);
    cudaGetSymbolAddress((void**)&wihh, g_wihh);
    cudaGetSymbolAddress((void**)&wihl, g_wihl);

    conv_split<<<(VOCAB * 256 + 255) / 256, 256>>>(emb, embh, embl, VOCAB * 256);
    conv_split<<<(D3H * 256 + 255) / 256, 256>>>(w_ih, wihh, wihl, D3H * 256);
    gi_hmma<<<dim3((SS * BB) / 128, D3H / 128), 256, gi_smem>>>(x, b_ih);
    gru_persistent<<<NCTA, 512, rec_smem>>>(w_hh, b_hh);
    fc_lsm<<<SS, 256>>>(fc_w, fc_b, out);
}

// round 13
// speedup vs baseline: 2.4848x; 1.0329x over previous
#include <cuda_runtime.h>
#include <cuda_fp16.h>
#include <math.h>

#define VOCAB 32000
#define D_IN  512
#define D_H   1024
#define D3H   3072
#define D_OUT 64
#define BB    64
#define SS    256
#define NCTA  128

typedef unsigned long long u64t;
typedef unsigned int u32t;

// ---------------- scratch (static device globals; zero-init at load) ----------
// gi transposed: [3H rows][S*B cols]  (row = gate*1024+j, col = s*64+b)
__device__ float g_gi[(size_t)D3H * SS * BB];
// h fp32 transposed: [s][j][b]  (exact, consumed by fc and z-path)
__device__ float g_hs[(size_t)SS * D_H * BB];
__device__ float g_h0[D_H * BB];                // all-zero h(-1), never written
// MMA-ready fp16 hi/lo split of h: word[k2*64+b] = (h[2k2][b], h[2k2+1][b])
__device__ u32t g_hmh[(D_H / 2) * BB];
__device__ u32t g_hml[(D_H / 2) * BB];
__device__ u32t g_hmz[(D_H / 2) * BB];          // zeros (step 0)
// fp16 hi/lo splits (u32-packed k-pairs) for the HMMA gi GEMM
__device__ u32t g_embh[(size_t)VOCAB * (D_IN / 2)];
__device__ u32t g_embl[(size_t)VOCAB * (D_IN / 2)];
__device__ u32t g_wihh[(size_t)D3H * (D_IN / 2)];
__device__ u32t g_wihl[(size_t)D3H * (D_IN / 2)];

// ---------------- grid barrier state (R3/R6/R8 proven protocol) ----------------
__device__ unsigned g_cnt = 0;
__device__ volatile unsigned g_flag = 0;        // cumulative barriers passed (monotonic)

// ---------------- helpers -------------------------------------------------------
__device__ __forceinline__ void fma2(u64t& c, u64t a, u64t b) {
    asm("fma.rn.f32x2 %0, %1, %2, %0;" : "+l"(c) : "l"(a), "l"(b));
}
__device__ __forceinline__ float2 up2(u64t v) {
    float2 r;
    asm("mov.b64 {%0, %1}, %2;" : "=f"(r.x), "=f"(r.y) : "l"(v));
    return r;
}
__device__ __forceinline__ u64t dup64(float w) {
    u64t r;
    asm("mov.b64 %0, {%1, %1};" : "=l"(r) : "f"(w));
    return r;
}
// mma.sync m16n8k16 f16 -> f32 (sm_80 baseline PTX; compiles on base sm_103)
__device__ __forceinline__ void mma16816(float* d, u32t a0, u32t a1, u32t a2, u32t a3,
                                         u32t b0, u32t b1) {
    asm volatile(
        "mma.sync.aligned.m16n8k16.row.col.f32.f16.f16.f32 "
        "{%0,%1,%2,%3}, {%4,%5,%6,%7}, {%8,%9}, {%0,%1,%2,%3};"
        : "+f"(d[0]), "+f"(d[1]), "+f"(d[2]), "+f"(d[3])
        : "r"(a0), "r"(a1), "r"(a2), "r"(a3), "r"(b0), "r"(b1));
}

// ==============================================================================
// Kernel 0: fp32 -> packed fp16 hi/lo split (k-pair u32). Grid-stride over pairs.
// ==============================================================================
__global__ __launch_bounds__(256) void conv_split(
    const float* __restrict__ src, u32t* __restrict__ dh, u32t* __restrict__ dl,
    int n2)
{
    int i = blockIdx.x * blockDim.x + threadIdx.x;
    if (i < n2) {
        float2 v = ((const float2*)src)[i];
        __half h0 = __float2half_rn(v.x);
        __half l0 = __float2half_rn(v.x - __half2float(h0));
        __half h1 = __float2half_rn(v.y);
        __half l1 = __float2half_rn(v.y - __half2float(h1));
        dh[i] = (u32t)__half_as_ushort(h0) | ((u32t)__half_as_ushort(h1) << 16);
        dl[i] = (u32t)__half_as_ushort(l0) | ((u32t)__half_as_ushort(l1) << 16);
    }
}

// ==============================================================================
// Kernel 1: gi GEMM via HMMA hi/lo.   (FROZEN from R11)
// ==============================================================================
#define GAH 0
#define GAL 2560
#define GBH 5120
#define GBL 7680
#define GBUF 10240      // u32 per buffer; 2 buffers = 20480 u32 = 80 KB

__global__ void __launch_bounds__(256, 1) gi_hmma(
    const int* __restrict__ x, const float* __restrict__ b_ih)
{
    extern __shared__ u32t smw[];

    const int tid  = threadIdx.x;
    const int lane = tid & 31;
    const int wid  = tid >> 5;
    const int m_blk = blockIdx.y * 128;
    const int n_blk = blockIdx.x * 128;
    const int wm = wid & 1, wn = wid >> 1;

    const int r0 = tid >> 2, q4 = tid & 3;
    int n0 = n_blk + r0, n1 = n0 + 64;
    const size_t tok0 = (size_t)x[(n0 & 63) * SS + (n0 >> 6)] * 256;
    const size_t tok1 = (size_t)x[(n1 & 63) * SS + (n1 >> 6)] * 256;
    const size_t wr0 = (size_t)(m_blk + r0) * 256;
    const size_t wr1 = (size_t)(m_blk + r0 + 64) * 256;

    float d[4][4][4];
#pragma unroll
    for (int mt = 0; mt < 4; mt++)
#pragma unroll
        for (int nt = 0; nt < 4; nt++)
#pragma unroll
            for (int u = 0; u < 4; u++) d[mt][nt][u] = 0.f;

    {
        u32t* B = smw;
        *(uint4*)&B[GAH + r0 * 20 + q4 * 4]        = *(const uint4*)&g_wihh[wr0 + q4 * 4];
        *(uint4*)&B[GAH + (r0 + 64) * 20 + q4 * 4] = *(const uint4*)&g_wihh[wr1 + q4 * 4];
        *(uint4*)&B[GAL + r0 * 20 + q4 * 4]        = *(const uint4*)&g_wihl[wr0 + q4 * 4];
        *(uint4*)&B[GAL + (r0 + 64) * 20 + q4 * 4] = *(const uint4*)&g_wihl[wr1 + q4 * 4];
        *(uint4*)&B[GBH + r0 * 20 + q4 * 4]        = *(const uint4*)&g_embh[tok0 + q4 * 4];
        *(uint4*)&B[GBH + (r0 + 64) * 20 + q4 * 4] = *(const uint4*)&g_embh[tok1 + q4 * 4];
        *(uint4*)&B[GBL + r0 * 20 + q4 * 4]        = *(const uint4*)&g_embl[tok0 + q4 * 4];
        *(uint4*)&B[GBL + (r0 + 64) * 20 + q4 * 4] = *(const uint4*)&g_embl[tok1 + q4 * 4];
    }
    __syncthreads();

    for (int ch = 0; ch < 16; ch++) {
        uint4 va[4], vb[4];
        if (ch < 15) {
            int o = (ch + 1) * 16 + q4 * 4;
            va[0] = *(const uint4*)&g_wihh[wr0 + o];
            va[1] = *(const uint4*)&g_wihh[wr1 + o];
            va[2] = *(const uint4*)&g_wihl[wr0 + o];
            va[3] = *(const uint4*)&g_wihl[wr1 + o];
            vb[0] = *(const uint4*)&g_embh[tok0 + o];
            vb[1] = *(const uint4*)&g_embh[tok1 + o];
            vb[2] = *(const uint4*)&g_embl[tok0 + o];
            vb[3] = *(const uint4*)&g_embl[tok1 + o];
        }

        const u32t* S = smw + (ch & 1) * GBUF;
#pragma unroll
        for (int kt = 0; kt < 2; kt++) {
            const int k2b = kt * 8 + (lane & 3);
            u32t ah[4][4], al[4][4], bh[4][2], bl[4][2];
#pragma unroll
            for (int mt = 0; mt < 4; mt++) {
                int r = wm * 64 + mt * 16 + (lane >> 2);
                ah[mt][0] = S[GAH + r * 20 + k2b];
                ah[mt][1] = S[GAH + (r + 8) * 20 + k2b];
                ah[mt][2] = S[GAH + r * 20 + k2b + 4];
                ah[mt][3] = S[GAH + (r + 8) * 20 + k2b + 4];
                al[mt][0] = S[GAL + r * 20 + k2b];
                al[mt][1] = S[GAL + (r + 8) * 20 + k2b];
                al[mt][2] = S[GAL + r * 20 + k2b + 4];
                al[mt][3] = S[GAL + (r + 8) * 20 + k2b + 4];
            }
#pragma unroll
            for (int nt = 0; nt < 4; nt++) {
                int c = wn * 32 + nt * 8 + (lane >> 2);
                bh[nt][0] = S[GBH + c * 20 + k2b];
                bh[nt][1] = S[GBH + c * 20 + k2b + 4];
                bl[nt][0] = S[GBL + c * 20 + k2b];
                bl[nt][1] = S[GBL + c * 20 + k2b + 4];
            }
#pragma unroll
            for (int mt = 0; mt < 4; mt++)
#pragma unroll
                for (int nt = 0; nt < 4; nt++) {
                    mma16816(d[mt][nt], ah[mt][0], ah[mt][1], ah[mt][2], ah[mt][3],
                             bh[nt][0], bh[nt][1]);
                    mma16816(d[mt][nt], ah[mt][0], ah[mt][1], ah[mt][2], ah[mt][3],
                             bl[nt][0], bl[nt][1]);
                    mma16816(d[mt][nt], al[mt][0], al[mt][1], al[mt][2], al[mt][3],
                             bh[nt][0], bh[nt][1]);
                }
        }

        if (ch < 15) {
            u32t* B = smw + ((ch + 1) & 1) * GBUF;
            *(uint4*)&B[GAH + r0 * 20 + q4 * 4]        = va[0];
            *(uint4*)&B[GAH + (r0 + 64) * 20 + q4 * 4] = va[1];
            *(uint4*)&B[GAL + r0 * 20 + q4 * 4]        = va[2];
            *(uint4*)&B[GAL + (r0 + 64) * 20 + q4 * 4] = va[3];
            *(uint4*)&B[GBH + r0 * 20 + q4 * 4]        = vb[0];
            *(uint4*)&B[GBH + (r0 + 64) * 20 + q4 * 4] = vb[1];
            *(uint4*)&B[GBL + r0 * 20 + q4 * 4]        = vb[2];
            *(uint4*)&B[GBL + (r0 + 64) * 20 + q4 * 4] = vb[3];
            __syncthreads();
        }
    }

#pragma unroll
    for (int mt = 0; mt < 4; mt++) {
        int rlo = m_blk + wm * 64 + mt * 16 + (lane >> 2);
        float b0 = b_ih[rlo], b1 = b_ih[rlo + 8];
#pragma unroll
        for (int nt = 0; nt < 4; nt++) {
            int c = n_blk + wn * 32 + nt * 8 + 2 * (lane & 3);
            *(float2*)&g_gi[(size_t)rlo * (SS * BB) + c] =
                make_float2(d[mt][nt][0] + b0, d[mt][nt][1] + b0);
            *(float2*)&g_gi[(size_t)(rlo + 8) * (SS * BB) + c] =
                make_float2(d[mt][nt][2] + b1, d[mt][nt][3] + b1);
        }
    }
}

// ==============================================================================
// Kernel 2: PERSISTENT GRU, HMMA recurrence — direct-LDG fragments,
// no SMEM staging, no mainloop syncs. h stored MMA-ready in global.
// ==============================================================================
#define WH_O   0            // [512 k2][24] fp16x2 hi : 12288 words
#define WL_O   12288        // lo                     : 12288 words
#define RED_O  24576        // [4][64][30] float = 7680 words
#define EX_O   32256        // ushort ex_h[512], ex_l[512] = 512 words
#define SM_WORDS 32768      // 131072 bytes

// load chunk g's A fragments (2 its x {ah0-3, al0-3}) straight from global
__device__ __forceinline__ void ldA(const u32t* __restrict__ hmh,
                                    const u32t* __restrict__ hml,
                                    int g, int ks, int mtb, int lane, u32t* A)
{
#pragma unroll
    for (int it = 0; it < 2; it++) {
        int tl = ks + it * 4;
        int ka = tl * 8 + (lane & 3);
        const u32t* ph = hmh + (size_t)(g * 64 + ka) * 64 + mtb + (lane >> 2);
        const u32t* pl = hml + (size_t)(g * 64 + ka) * 64 + mtb + (lane >> 2);
        A[it*8 + 0] = ph[0];
        A[it*8 + 1] = ph[8];
        A[it*8 + 2] = ph[256];          // (ka+4)*64
        A[it*8 + 3] = ph[264];
        A[it*8 + 4] = pl[0];
        A[it*8 + 5] = pl[8];
        A[it*8 + 6] = pl[256];
        A[it*8 + 7] = pl[264];
    }
}

__global__ void __launch_bounds__(512, 1) gru_persistent(
    const float* __restrict__ w_hh, const float* __restrict__ b_hh)
{
    extern __shared__ u32t smw[];
    float* redf = (float*)(smw + RED_O);
    unsigned short* ex = (unsigned short*)(smw + EX_O);   // ex_h[512], ex_l[512]

    const int tid  = threadIdx.x;
    const int j0   = blockIdx.x * 8;
    const int wid  = tid >> 5;
    const int lane = tid & 31;

    // ---- one-time: W slice -> fp16 hi/lo, layout [k2 global][24 n] ----
    {
        int k2 = tid;
#pragma unroll 1
        for (int n = 0; n < 24; n++) {
            int g = n >> 3, jj = n & 7;
            float2 wv = *(const float2*)(w_hh + (size_t)(g * D_H + j0 + jj) * D_H + k2 * 2);
            __half h0 = __float2half_rn(wv.x);
            __half l0 = __float2half_rn(wv.x - __half2float(h0));
            __half h1 = __float2half_rn(wv.y);
            __half l1 = __float2half_rn(wv.y - __half2float(h1));
            smw[WH_O + k2 * 24 + n] = (u32t)__half_as_ushort(h0) | ((u32t)__half_as_ushort(h1) << 16);
            smw[WL_O + k2 * 24 + n] = (u32t)__half_as_ushort(l0) | ((u32t)__half_as_ushort(l1) << 16);
        }
    }

    unsigned base = 0;
    if (tid == 0) base = g_flag;
    __syncthreads();

    const int mt = wid & 3;
    const int ks = wid >> 2;
    const int mtb = mt * 16;
    const int ncol = lane >> 2;
    const int ejj = tid >> 6, eb = tid & 63;
    const int ej  = j0 + ejj;
    const float bhr = b_hh[ej], bhz = b_hh[D_H + ej], bhn = b_hh[2 * D_H + ej];

    for (int s = 0; s < SS; s++) {
        const float* hp32 = (s == 0) ? g_h0 : (g_hs + (size_t)(s - 1) * D_H * BB);
        const u32t* hmh = (s == 0) ? g_hmz : g_hmh;
        const u32t* hml = (s == 0) ? g_hmz : g_hml;

        // ---- chunk 0 fragment loads first (post-barrier critical path) ----
        u32t A[2][16];
        ldA(hmh, hml, 0, ks, mtb, lane, A[0]);

        // ---- epilogue operand prefetch (overlaps) ----
        const float* gip = g_gi + (size_t)s * 64 + (size_t)ej * (SS * BB) + eb;
        float e_gir = gip[0];
        float e_giz = gip[(size_t)D_H * SS * BB];
        float e_gin = gip[(size_t)2 * D_H * SS * BB];
        float e_hp  = hp32[(size_t)ej * 64 + eb];

        float d[3][4];
#pragma unroll
        for (int nt = 0; nt < 3; nt++)
#pragma unroll
            for (int u = 0; u < 4; u++) d[nt][u] = 0.f;

#pragma unroll
        for (int g = 0; g < 8; g++) {
            if (g < 7) ldA(hmh, hml, g + 1, ks, mtb, lane, A[(g + 1) & 1]);

            const u32t* Ac = A[g & 1];
#pragma unroll
            for (int it = 0; it < 2; it++) {
                int tl = ks + it * 4;
                int ka = tl * 8 + (lane & 3);
                int kw = (g * 64 + ka) * 24 + ncol;
#pragma unroll
                for (int nt = 0; nt < 3; nt++) {
                    u32t bh0 = smw[WH_O + kw + nt * 8];
                    u32t bh1 = smw[WH_O + kw + 96 + nt * 8];
                    u32t bl0 = smw[WL_O + kw + nt * 8];
                    u32t bl1 = smw[WL_O + kw + 96 + nt * 8];
                    mma16816(d[nt], Ac[it*8+0], Ac[it*8+1], Ac[it*8+2], Ac[it*8+3],
                             bh0, bh1);
                    mma16816(d[nt], Ac[it*8+0], Ac[it*8+1], Ac[it*8+2], Ac[it*8+3],
                             bl0, bl1);
                    mma16816(d[nt], Ac[it*8+4], Ac[it*8+5], Ac[it*8+6], Ac[it*8+7],
                             bh0, bh1);
                }
            }
        }

        // ---- D fragments -> red [4 ks][64 m][30 n-pad] ----
#pragma unroll
        for (int nt = 0; nt < 3; nt++) {
            int rb = (ks * 64 + mt * 16 + (lane >> 2)) * 30 + nt * 8 + 2 * (lane & 3);
            *(float2*)&redf[rb]       = make_float2(d[nt][0], d[nt][1]);
            *(float2*)&redf[rb + 240] = make_float2(d[nt][2], d[nt][3]);
        }
        __syncthreads();

        // ---- gate epilogue: 512 outputs, 1 per thread ----
        {
            float ghr = 0.f, ghz = 0.f, ghn = 0.f;
#pragma unroll
            for (int k = 0; k < 4; k++) {
                int rb = (k * 64 + eb) * 30;
                ghr += redf[rb + ejj];
                ghz += redf[rb + 8 + ejj];
                ghn += redf[rb + 16 + ejj];
            }
            float r = 1.f / (1.f + expf(-(e_gir + ghr + bhr)));
            float z = 1.f / (1.f + expf(-(e_giz + ghz + bhz)));
            float n = tanhf(e_gin + r * (ghn + bhn));
            float h = (1.f - z) * n + z * e_hp;
            g_hs[(size_t)s * D_H * BB + (size_t)ej * 64 + eb] = h;
            __half hh = __float2half_rn(h);
            __half hl = __float2half_rn(h - __half2float(hh));
            ex[ejj * 64 + eb]       = __half_as_ushort(hh);
            ex[512 + ejj * 64 + eb] = __half_as_ushort(hl);
        }
        __syncthreads();

        // ---- pack MMA-ready words: word(k2, b) = (h[2k2][b], h[2k2+1][b]) ----
        if (tid < 256) {
            int k2l = tid >> 6, b = tid & 63;
            u32t wh = (u32t)ex[(2 * k2l) * 64 + b]
                    | ((u32t)ex[(2 * k2l + 1) * 64 + b] << 16);
            u32t wl = (u32t)ex[512 + (2 * k2l) * 64 + b]
                    | ((u32t)ex[512 + (2 * k2l + 1) * 64 + b] << 16);
            int k2g = 4 * blockIdx.x + k2l;
            g_hmh[k2g * 64 + b] = wh;
            g_hml[k2g * 64 + b] = wl;
        }

        // ---- grid barrier (proven) ----
        __syncthreads();
        if (tid == 0) {
            __threadfence();
            unsigned target = base + (unsigned)(s + 1);
            unsigned old = atomicAdd(&g_cnt, 1u);
            if (old == NCTA - 1) {
                atomicExch(&g_cnt, 0u);
                __threadfence();
                atomicExch((unsigned*)&g_flag, target);
            } else {
                while (g_flag < target) { }
            }
            __threadfence();
        }
        __syncthreads();
    }
}

// ==============================================================================
// Kernel 3: fc + log_softmax (unchanged)
// ==============================================================================
__global__ __launch_bounds__(256) void fc_lsm(
    const float* __restrict__ fc_w, const float* __restrict__ fc_b,
    float* __restrict__ out)
{
    __shared__ float hst[32 * 64];
    __shared__ float wst[64 * 36];
    __shared__ float L  [64 * 65];

    const int tid = threadIdx.x;
    const int s   = blockIdx.x;
    const float* hs_s = g_hs + (size_t)s * D_H * BB;
    const int og = tid & 15, bg = tid >> 4;

    u64t acc[2][4];
#pragma unroll
    for (int u = 0; u < 2; u++)
#pragma unroll
        for (int v = 0; v < 4; v++) acc[u][v] = 0ull;
    u64t* hst8 = (u64t*)hst;

    for (int k0 = 0; k0 < D_H; k0 += 32) {
        __syncthreads();
#pragma unroll
        for (int i = 0; i < 2; i++) {
            int q = tid + i * 256;
            int kl = q >> 4, bq = q & 15;
            *(float4*)(hst + kl*64 + bq*4) =
                *(const float4*)(hs_s + (size_t)(k0 + kl) * 64 + bq * 4);
        }
#pragma unroll
        for (int i = 0; i < 2; i++) {
            int q = tid + i * 256;
            int o = q >> 3, kq = q & 7;
            *(float4*)(wst + o*36 + kq*4) =
                *(const float4*)(fc_w + (size_t)o * D_H + k0 + kq * 4);
        }
        __syncthreads();
#pragma unroll 4
        for (int kk = 0; kk < 32; kk++) {
            u64t h0 = hst8[kk*32 + bg*2 + 0];
            u64t h1 = hst8[kk*32 + bg*2 + 1];
#pragma unroll
            for (int v = 0; v < 4; v++) {
                u64t wd = dup64(wst[(og*4 + v)*36 + kk]);
                fma2(acc[0][v], h0, wd);
                fma2(acc[1][v], h1, wd);
            }
        }
    }

    __syncthreads();
#pragma unroll
    for (int u = 0; u < 2; u++) {
#pragma unroll
        for (int v = 0; v < 4; v++) {
            float2 p = up2(acc[u][v]);
            int o  = og * 4 + v;
            int b0 = bg * 4 + u * 2;
            float bias = fc_b[o];
            L[(b0 + 0)*65 + o] = p.x + bias;
            L[(b0 + 1)*65 + o] = p.y + bias;
        }
    }
    __syncthreads();

    const int w = tid >> 5, lane = tid & 31;
#pragma unroll
    for (int rr = 0; rr < 8; rr++) {
        int b = w * 8 + rr;
        float v0 = L[b*65 + lane], v1 = L[b*65 + 32 + lane];
        float mx = fmaxf(v0, v1);
#pragma unroll
        for (int o = 16; o > 0; o >>= 1) mx = fmaxf(mx, __shfl_xor_sync(0xffffffffu, mx, o));
        float se = expf(v0 - mx) + expf(v1 - mx);
#pragma unroll
        for (int o = 16; o > 0; o >>= 1) se += __shfl_xor_sync(0xffffffffu, se, o);
        float lse = logf(se) + mx;
        float* op = out + ((size_t)b * SS + s) * D_OUT;
        op[lane]      = v0 - lse;
        op[lane + 32] = v1 - lse;
    }
}

// ==============================================================================
extern "C" void kernel_launch(void* const* d_in, const int* in_sizes, int n_in,
                              void* d_out, int out_size)
{
    (void)in_sizes; (void)n_in; (void)out_size;
    const int*   x    = (const int*)  d_in[0];
    const float* emb  = (const float*)d_in[1];
    const float* w_ih = (const float*)d_in[2];
    const float* w_hh = (const float*)d_in[3];
    const float* b_ih = (const float*)d_in[4];
    const float* b_hh = (const float*)d_in[5];
    const float* fc_w = (const float*)d_in[6];
    const float* fc_b = (const float*)d_in[7];
    float* out = (float*)d_out;

    const int rec_smem = SM_WORDS * 4;   // 131072 B
    cudaFuncSetAttribute(gru_persistent,
                         cudaFuncAttributeMaxDynamicSharedMemorySize, rec_smem);
    const int gi_smem = 2 * GBUF * 4;    // 81920 B
    cudaFuncSetAttribute(gi_hmma,
                         cudaFuncAttributeMaxDynamicSharedMemorySize, gi_smem);

    u32t *embh, *embl, *wihh, *wihl;
    cudaGetSymbolAddress((void**)&embh, g_embh);
    cudaGetSymbolAddress((void**)&embl, g_embl);
    cudaGetSymbolAddress((void**)&wihh, g_wihh);
    cudaGetSymbolAddress((void**)&wihl, g_wihl);

    conv_split<<<(VOCAB * 256 + 255) / 256, 256>>>(emb, embh, embl, VOCAB * 256);
    conv_split<<<(D3H * 256 + 255) / 256, 256>>>(w_ih, wihh, wihl, D3H * 256);
    gi_hmma<<<dim3((SS * BB) / 128, D3H / 128), 256, gi_smem>>>(x, b_ih);
    gru_persistent<<<NCTA, 512, rec_smem>>>(w_hh, b_hh);
    fc_lsm<<<SS, 256>>>(fc_w, fc_b, out);
}